// round 3
// baseline (speedup 1.0000x reference)
#include <cuda_runtime.h>
#include <cuda_bf16.h>

#define N_NODES 100000
#define DIM     128
#define KNB     16

// Scratch: X1[n] = latents[n] @ W1[0:128,:] + b1 ; X2[n] = latents[n] @ W1[128:256,:]
__device__ float g_X1[(size_t)N_NODES * DIM];
__device__ float g_X2[(size_t)N_NODES * DIM];

typedef unsigned long long u64;

// ---- packed f32x2 helpers (Blackwell, PTX 8.6, sm_100+) --------------------
__device__ __forceinline__ u64 pack_dup(float x) {
    u64 r;
    asm("mov.b64 %0, {%1, %1};" : "=l"(r) : "f"(x));
    return r;
}
__device__ __forceinline__ void fma2(u64& d, u64 a, u64 b) {
    asm("fma.rn.f32x2 %0, %1, %2, %0;" : "+l"(d) : "l"(a), "l"(b));
}
__device__ __forceinline__ float2 unpack2(u64 v) {
    float2 f;
    asm("mov.b64 {%0, %1}, %2;" : "=f"(f.x), "=f"(f.y) : "l"(v));
    return f;
}

// ---------------------------------------------------------------------------
// Kernel 1: GEMM  [100000 x 128] @ [128 x 128]  (x2 halves via blockIdx.y)
// BM=128, BN=128, BK=8, 256 threads, 8x8 per-thread tile as 8x4 f32x2 pairs,
// double-buffered smem, packed fma.rn.f32x2 mainloop.
// ---------------------------------------------------------------------------
#define BM 128
#define BN 128
#define BK 8

__global__ __launch_bounds__(256) void mlp1_gemm(const float* __restrict__ lat,
                                                 const float* __restrict__ W1,
                                                 const float* __restrict__ b1) {
    const int half = blockIdx.y;
    const float* __restrict__ B = W1 + (half ? (DIM * DIM) : 0); // row-major [256][128]
    float* __restrict__ outp = half ? g_X2 : g_X1;
    const int m0 = blockIdx.x * BM;

    __shared__ __align__(16) float As[2][BK][BM + 4]; // transposed A tile, padded (132*4B = 16B-mult)
    __shared__ __align__(16) float Bs[2][BK][BN];

    const int tid = threadIdx.x;            // 0..255
    const int tm  = (tid >> 4) * 8;         // 0..120
    const int tn  = (tid & 15) * 8;         // 0..120

    // A-load coords: one float4 per thread per stage.
    const int la_m  = tid >> 1;              // 0..127
    const int la_kq = (tid & 1) * 4;         // 0 or 4
    int la_gm = m0 + la_m;
    if (la_gm >= N_NODES) la_gm = N_NODES - 1;   // clamp (stores are guarded)
    const float* la_ptr = lat + (size_t)la_gm * DIM + la_kq;

    // B-load coords: one float4 per thread per stage.
    const int lb_k = tid >> 5;               // 0..7
    const int lb_c = (tid & 31) * 4;         // 0..124
    const float* lb_ptr = B + (size_t)lb_k * DIM + lb_c;

    u64 acc[8][4];
#pragma unroll
    for (int i = 0; i < 8; i++)
#pragma unroll
        for (int j = 0; j < 4; j++) acc[i][j] = 0ull;

    // Prefetch stage 0
    {
        float4 va = *(const float4*)(la_ptr);
        As[0][la_kq + 0][la_m] = va.x;
        As[0][la_kq + 1][la_m] = va.y;
        As[0][la_kq + 2][la_m] = va.z;
        As[0][la_kq + 3][la_m] = va.w;
        *(float4*)(&Bs[0][lb_k][lb_c]) = *(const float4*)(lb_ptr);
    }
    __syncthreads();

    int s = 0;
    for (int k0 = 0; k0 < DIM; k0 += BK, s ^= 1) {
        const int nk0 = k0 + BK;
        if (nk0 < DIM) {
            float4 va = *(const float4*)(la_ptr + nk0);
            As[s ^ 1][la_kq + 0][la_m] = va.x;
            As[s ^ 1][la_kq + 1][la_m] = va.y;
            As[s ^ 1][la_kq + 2][la_m] = va.z;
            As[s ^ 1][la_kq + 3][la_m] = va.w;
            *(float4*)(&Bs[s ^ 1][lb_k][lb_c]) = *(const float4*)(lb_ptr + (size_t)nk0 * DIM);
        }

#pragma unroll
        for (int k = 0; k < BK; k++) {
            float a[8];
            *(float4*)(a)     = *(const float4*)(&As[s][k][tm]);
            *(float4*)(a + 4) = *(const float4*)(&As[s][k][tm + 4]);
            ulonglong2 bv0 = *(const ulonglong2*)(&Bs[s][k][tn]);
            ulonglong2 bv1 = *(const ulonglong2*)(&Bs[s][k][tn + 4]);
            u64 b0 = bv0.x, b1 = bv0.y, b2 = bv1.x, b3 = bv1.y;
#pragma unroll
            for (int i = 0; i < 8; i++) {
                u64 ad = pack_dup(a[i]);
                fma2(acc[i][0], ad, b0);
                fma2(acc[i][1], ad, b1);
                fma2(acc[i][2], ad, b2);
                fma2(acc[i][3], ad, b3);
            }
        }
        __syncthreads();
    }

    // Epilogue: add bias (half 0 only), store two float4 per row.
    float bias[8];
#pragma unroll
    for (int j = 0; j < 8; j++) bias[j] = (half == 0) ? b1[tn + j] : 0.f;

#pragma unroll
    for (int i = 0; i < 8; i++) {
        const int gm = m0 + tm + i;
        if (gm < N_NODES) {
            float2 p0 = unpack2(acc[i][0]);
            float2 p1 = unpack2(acc[i][1]);
            float2 p2 = unpack2(acc[i][2]);
            float2 p3 = unpack2(acc[i][3]);
            float4 v0, v1;
            v0.x = p0.x + bias[0];
            v0.y = p0.y + bias[1];
            v0.z = p1.x + bias[2];
            v0.w = p1.y + bias[3];
            v1.x = p2.x + bias[4];
            v1.y = p2.y + bias[5];
            v1.z = p3.x + bias[6];
            v1.w = p3.y + bias[7];
            float* o = outp + (size_t)gm * DIM + tn;
            *(float4*)(o)     = v0;
            *(float4*)(o + 4) = v1;
        }
    }
}

// ---------------------------------------------------------------------------
// Kernel 2: fused gather / score / softmax / weighted sum. One warp per node.
// Two-pass: pass1 gathers X2 rows for scores; pass2 re-gathers latents rows
// for the weighted sum. Each row still read exactly once; dropping the 64-reg
// latents buffer roughly doubles occupancy.
// ---------------------------------------------------------------------------
__global__ __launch_bounds__(256) void attend_kernel(const float* __restrict__ lat,
                                                     const int* __restrict__ nbr,
                                                     const float* __restrict__ W2,
                                                     float* __restrict__ out) {
    __shared__ float s_w2[DIM];
    const int tid = threadIdx.x;
    if (tid < DIM) s_w2[tid] = W2[tid];
    __syncthreads();

    const int n = blockIdx.x * (blockDim.x >> 5) + (tid >> 5);
    if (n >= N_NODES) return;
    const int lane = tid & 31;

    const float4 x1  = *(const float4*)(g_X1 + (size_t)n * DIM + lane * 4);
    const float4 w2v = *(const float4*)(s_w2 + lane * 4);

    int js[KNB];
    {
        const int4* p = (const int4*)(nbr + (size_t)n * KNB);
#pragma unroll
        for (int q = 0; q < 4; q++) {
            int4 v = __ldg(p + q);
            js[q * 4 + 0] = v.x;
            js[q * 4 + 1] = v.y;
            js[q * 4 + 2] = v.z;
            js[q * 4 + 3] = v.w;
        }
    }

    // Pass 1: scores from X2 gather.
    float sc[KNB];
#pragma unroll 8
    for (int k = 0; k < KNB; k++) {
        const float4 x2 = *(const float4*)(g_X2 + (size_t)js[k] * DIM + lane * 4);
        float p = fmaxf(x1.x + x2.x, 0.f) * w2v.x;
        p = fmaf(fmaxf(x1.y + x2.y, 0.f), w2v.y, p);
        p = fmaf(fmaxf(x1.z + x2.z, 0.f), w2v.z, p);
        p = fmaf(fmaxf(x1.w + x2.w, 0.f), w2v.w, p);
        sc[k] = p;
    }

    // Warp-reduce each of the 16 scores (result identical in all lanes).
#pragma unroll
    for (int k = 0; k < KNB; k++) {
        float p = sc[k];
        p += __shfl_xor_sync(0xffffffffu, p, 16);
        p += __shfl_xor_sync(0xffffffffu, p, 8);
        p += __shfl_xor_sync(0xffffffffu, p, 4);
        p += __shfl_xor_sync(0xffffffffu, p, 2);
        p += __shfl_xor_sync(0xffffffffu, p, 1);
        sc[k] = p;
    }

    // Softmax over K=16 (b2 cancels).
    float m = sc[0];
#pragma unroll
    for (int k = 1; k < KNB; k++) m = fmaxf(m, sc[k]);
    float ssum = 0.f;
#pragma unroll
    for (int k = 0; k < KNB; k++) {
        sc[k] = __expf(sc[k] - m);
        ssum += sc[k];
    }
    const float inv = 1.f / ssum;

    // Pass 2: weighted sum over gathered latents rows (unroll capped to limit
    // live registers while keeping 4 gathers in flight).
    float4 acc = make_float4(0.f, 0.f, 0.f, 0.f);
#pragma unroll 4
    for (int k = 0; k < KNB; k++) {
        const float4 lv = __ldg((const float4*)(lat + (size_t)js[k] * DIM + lane * 4));
        const float w = sc[k] * inv;
        acc.x = fmaf(w, lv.x, acc.x);
        acc.y = fmaf(w, lv.y, acc.y);
        acc.z = fmaf(w, lv.z, acc.z);
        acc.w = fmaf(w, lv.w, acc.w);
    }
    *(float4*)(out + (size_t)n * DIM + lane * 4) = acc;
}

// ---------------------------------------------------------------------------
// Launch
// ---------------------------------------------------------------------------
extern "C" void kernel_launch(void* const* d_in, const int* in_sizes, int n_in,
                              void* d_out, int out_size) {
    const float* latents   = (const float*)d_in[0];
    const int*   neighbors = (const int*)d_in[1];   // int32 (JAX x64-disabled)
    const float* W1        = (const float*)d_in[2];
    const float* b1        = (const float*)d_in[3];
    const float* W2        = (const float*)d_in[4];
    // d_in[5] = b2: constant shift across softmax axis -> cancels, unused.
    float* out = (float*)d_out;

    (void)in_sizes; (void)n_in; (void)out_size;

    dim3 ggrid((N_NODES + BM - 1) / BM, 2);
    mlp1_gemm<<<ggrid, 256>>>(latents, W1, b1);

    const int warps_per_block = 8;
    const int blocks = (N_NODES + warps_per_block - 1) / warps_per_block;
    attend_kernel<<<blocks, warps_per_block * 32>>>(latents, neighbors, W2, out);
}

// round 5
// speedup vs baseline: 1.2169x; 1.2169x over previous
#include <cuda_runtime.h>
#include <cuda_bf16.h>

#define N_NODES 100000
#define DIM     128
#define KNB     16

// Scratch: X1[n] = latents[n] @ W1[0:128,:] + b1 ; X2[n] = latents[n] @ W1[128:256,:]
__device__ float g_X1[(size_t)N_NODES * DIM];
__device__ float g_X2[(size_t)N_NODES * DIM];

typedef unsigned long long u64;

// ---- packed f32x2 helpers (Blackwell, sm_100+) ------------------------------
__device__ __forceinline__ u64 pack_dup(float x) {
    u64 r;
    asm("mov.b64 %0, {%1, %1};" : "=l"(r) : "f"(x));
    return r;
}
__device__ __forceinline__ void fma2(u64& d, u64 a, u64 b) {
    asm("fma.rn.f32x2 %0, %1, %2, %0;" : "+l"(d) : "l"(a), "l"(b));
}
__device__ __forceinline__ float2 unpack2(u64 v) {
    float2 f;
    asm("mov.b64 {%0, %1}, %2;" : "=f"(f.x), "=f"(f.y) : "l"(v));
    return f;
}

// ---- cache-hinted memory ops (createpolicy + cache_hint: legal for v4.f32) ---
__device__ __forceinline__ u64 make_evict_last_policy() {
    u64 pol;
    asm("createpolicy.fractional.L2::evict_last.b64 %0, 1.0;" : "=l"(pol));
    return pol;
}
__device__ __forceinline__ float4 ldg_keep(const float* p, u64 pol) {
    float4 v;
    asm("ld.global.nc.L2::cache_hint.v4.f32 {%0,%1,%2,%3}, [%4], %5;"
        : "=f"(v.x), "=f"(v.y), "=f"(v.z), "=f"(v.w) : "l"(p), "l"(pol));
    return v;
}
__device__ __forceinline__ void stg_keep(float* p, float4 v, u64 pol) {
    asm volatile("st.global.L2::cache_hint.v4.f32 [%0], {%1,%2,%3,%4}, %5;"
                 :: "l"(p), "f"(v.x), "f"(v.y), "f"(v.z), "f"(v.w), "l"(pol) : "memory");
}

// ---------------------------------------------------------------------------
// Kernel 1: GEMM  [100000 x 128] @ [128 x 128]  (x2 halves via blockIdx.y)
// BM=128, BN=128, BK=8, 256 threads, 8x8 per-thread tile as 8x4 f32x2 pairs,
// double-buffered smem, packed fma.rn.f32x2 mainloop.
// A-tile (latents) loads + X2 stores are evict_last so attend finds them in L2.
// ---------------------------------------------------------------------------
#define BM 128
#define BN 128
#define BK 8

__global__ __launch_bounds__(256) void mlp1_gemm(const float* __restrict__ lat,
                                                 const float* __restrict__ W1,
                                                 const float* __restrict__ b1) {
    const int half = blockIdx.y;
    const float* __restrict__ B = W1 + (half ? (DIM * DIM) : 0); // row-major [256][128]
    float* __restrict__ outp = half ? g_X2 : g_X1;
    const int m0 = blockIdx.x * BM;
    const u64 pol = make_evict_last_policy();

    __shared__ __align__(16) float As[2][BK][BM + 4]; // transposed A tile, padded
    __shared__ __align__(16) float Bs[2][BK][BN];

    const int tid = threadIdx.x;            // 0..255
    const int tm  = (tid >> 4) * 8;         // 0..120
    const int tn  = (tid & 15) * 8;         // 0..120

    // A-load coords: one float4 per thread per stage.
    const int la_m  = tid >> 1;              // 0..127
    const int la_kq = (tid & 1) * 4;         // 0 or 4
    int la_gm = m0 + la_m;
    if (la_gm >= N_NODES) la_gm = N_NODES - 1;   // clamp (stores are guarded)
    const float* la_ptr = lat + (size_t)la_gm * DIM + la_kq;

    // B-load coords: one float4 per thread per stage.
    const int lb_k = tid >> 5;               // 0..7
    const int lb_c = (tid & 31) * 4;         // 0..124
    const float* lb_ptr = B + (size_t)lb_k * DIM + lb_c;

    u64 acc[8][4];
#pragma unroll
    for (int i = 0; i < 8; i++)
#pragma unroll
        for (int j = 0; j < 4; j++) acc[i][j] = 0ull;

    // Prefetch stage 0
    {
        float4 va = ldg_keep(la_ptr, pol);   // latents stay L2-resident for attend
        As[0][la_kq + 0][la_m] = va.x;
        As[0][la_kq + 1][la_m] = va.y;
        As[0][la_kq + 2][la_m] = va.z;
        As[0][la_kq + 3][la_m] = va.w;
        *(float4*)(&Bs[0][lb_k][lb_c]) = *(const float4*)(lb_ptr);
    }
    __syncthreads();

    int s = 0;
    for (int k0 = 0; k0 < DIM; k0 += BK, s ^= 1) {
        const int nk0 = k0 + BK;
        if (nk0 < DIM) {
            float4 va = ldg_keep(la_ptr + nk0, pol);
            As[s ^ 1][la_kq + 0][la_m] = va.x;
            As[s ^ 1][la_kq + 1][la_m] = va.y;
            As[s ^ 1][la_kq + 2][la_m] = va.z;
            As[s ^ 1][la_kq + 3][la_m] = va.w;
            *(float4*)(&Bs[s ^ 1][lb_k][lb_c]) = *(const float4*)(lb_ptr + (size_t)nk0 * DIM);
        }

#pragma unroll
        for (int k = 0; k < BK; k++) {
            float a[8];
            *(float4*)(a)     = *(const float4*)(&As[s][k][tm]);
            *(float4*)(a + 4) = *(const float4*)(&As[s][k][tm + 4]);
            ulonglong2 bv0 = *(const ulonglong2*)(&Bs[s][k][tn]);
            ulonglong2 bv1 = *(const ulonglong2*)(&Bs[s][k][tn + 4]);
            u64 b0 = bv0.x, b1 = bv0.y, b2 = bv1.x, b3 = bv1.y;
#pragma unroll
            for (int i = 0; i < 8; i++) {
                u64 ad = pack_dup(a[i]);
                fma2(acc[i][0], ad, b0);
                fma2(acc[i][1], ad, b1);
                fma2(acc[i][2], ad, b2);
                fma2(acc[i][3], ad, b3);
            }
        }
        __syncthreads();
    }

    // Epilogue: add bias (half 0 only), store two float4 per row.
    float bias[8];
#pragma unroll
    for (int j = 0; j < 8; j++) bias[j] = (half == 0) ? b1[tn + j] : 0.f;

#pragma unroll
    for (int i = 0; i < 8; i++) {
        const int gm = m0 + tm + i;
        if (gm < N_NODES) {
            float2 p0 = unpack2(acc[i][0]);
            float2 p1 = unpack2(acc[i][1]);
            float2 p2 = unpack2(acc[i][2]);
            float2 p3 = unpack2(acc[i][3]);
            float4 v0, v1;
            v0.x = p0.x + bias[0];
            v0.y = p0.y + bias[1];
            v0.z = p1.x + bias[2];
            v0.w = p1.y + bias[3];
            v1.x = p2.x + bias[4];
            v1.y = p2.y + bias[5];
            v1.z = p3.x + bias[6];
            v1.w = p3.y + bias[7];
            float* o = outp + (size_t)gm * DIM + tn;
            if (half) {            // X2 is gather-read next kernel: keep in L2
                stg_keep(o, v0, pol);
                stg_keep(o + 4, v1, pol);
            } else {               // X1 is streamed once: default policy
                *(float4*)(o)     = v0;
                *(float4*)(o + 4) = v1;
            }
        }
    }
}

// ---------------------------------------------------------------------------
// Kernel 2: fused gather / score / softmax / weighted sum. One warp per node.
// Single pass: X2[j] and latents[j] gathered together (one temporal-reuse
// window per neighbor row — this halved DRAM traffic vs the 2-pass variant).
// Gathers evict_last; streams (X1, nbr, out) evict-streaming.
// ---------------------------------------------------------------------------
__global__ __launch_bounds__(256) void attend_kernel(const float* __restrict__ lat,
                                                     const int* __restrict__ nbr,
                                                     const float* __restrict__ W2,
                                                     float* __restrict__ out) {
    __shared__ float s_w2[DIM];
    const int tid = threadIdx.x;
    if (tid < DIM) s_w2[tid] = W2[tid];
    __syncthreads();

    const int n = blockIdx.x * (blockDim.x >> 5) + (tid >> 5);
    if (n >= N_NODES) return;
    const int lane = tid & 31;
    const u64 pol = make_evict_last_policy();

    const float4 x1  = __ldcs((const float4*)(g_X1 + (size_t)n * DIM + lane * 4));
    const float4 w2v = *(const float4*)(s_w2 + lane * 4);

    int js[KNB];
    {
        const int4* p = (const int4*)(nbr + (size_t)n * KNB);
#pragma unroll
        for (int q = 0; q < 4; q++) {
            int4 v = __ldcs(p + q);
            js[q * 4 + 0] = v.x;
            js[q * 4 + 1] = v.y;
            js[q * 4 + 2] = v.z;
            js[q * 4 + 3] = v.w;
        }
    }

    float  sc[KNB];
    float4 lb[KNB];
#pragma unroll
    for (int k = 0; k < KNB; k++) {
        const size_t off = (size_t)js[k] * DIM + lane * 4;
        const float4 x2 = ldg_keep(g_X2 + off, pol);
        const float4 lv = ldg_keep(lat + off, pol);
        lb[k] = lv;
        float p = fmaxf(x1.x + x2.x, 0.f) * w2v.x;
        p = fmaf(fmaxf(x1.y + x2.y, 0.f), w2v.y, p);
        p = fmaf(fmaxf(x1.z + x2.z, 0.f), w2v.z, p);
        p = fmaf(fmaxf(x1.w + x2.w, 0.f), w2v.w, p);
        sc[k] = p;
    }

    // Warp-reduce each of the 16 scores (result identical in all lanes).
#pragma unroll
    for (int k = 0; k < KNB; k++) {
        float p = sc[k];
        p += __shfl_xor_sync(0xffffffffu, p, 16);
        p += __shfl_xor_sync(0xffffffffu, p, 8);
        p += __shfl_xor_sync(0xffffffffu, p, 4);
        p += __shfl_xor_sync(0xffffffffu, p, 2);
        p += __shfl_xor_sync(0xffffffffu, p, 1);
        sc[k] = p;
    }

    // Softmax over K=16 (b2 cancels).
    float m = sc[0];
#pragma unroll
    for (int k = 1; k < KNB; k++) m = fmaxf(m, sc[k]);
    float ssum = 0.f;
#pragma unroll
    for (int k = 0; k < KNB; k++) {
        sc[k] = __expf(sc[k] - m);
        ssum += sc[k];
    }
    const float inv = 1.f / ssum;

    float4 acc = make_float4(0.f, 0.f, 0.f, 0.f);
#pragma unroll
    for (int k = 0; k < KNB; k++) {
        const float w = sc[k] * inv;
        acc.x = fmaf(w, lb[k].x, acc.x);
        acc.y = fmaf(w, lb[k].y, acc.y);
        acc.z = fmaf(w, lb[k].z, acc.z);
        acc.w = fmaf(w, lb[k].w, acc.w);
    }
    __stcs((float4*)(out + (size_t)n * DIM + lane * 4), acc);
}

// ---------------------------------------------------------------------------
// Launch
// ---------------------------------------------------------------------------
extern "C" void kernel_launch(void* const* d_in, const int* in_sizes, int n_in,
                              void* d_out, int out_size) {
    const float* latents   = (const float*)d_in[0];
    const int*   neighbors = (const int*)d_in[1];   // int32 (JAX x64-disabled)
    const float* W1        = (const float*)d_in[2];
    const float* b1        = (const float*)d_in[3];
    const float* W2        = (const float*)d_in[4];
    // d_in[5] = b2: constant shift across softmax axis -> cancels, unused.
    float* out = (float*)d_out;

    (void)in_sizes; (void)n_in; (void)out_size;

    dim3 ggrid((N_NODES + BM - 1) / BM, 2);
    mlp1_gemm<<<ggrid, 256>>>(latents, W1, b1);

    const int warps_per_block = 8;
    const int blocks = (N_NODES + warps_per_block - 1) / warps_per_block;
    attend_kernel<<<blocks, warps_per_block * 32>>>(latents, neighbors, W2, out);
}

// round 7
// speedup vs baseline: 1.2190x; 1.0018x over previous
#include <cuda_runtime.h>
#include <cuda_bf16.h>
#include <cstdint>

#define N_NODES 100000
#define DIM     128
#define KNB     16

// Scratch tables.
__device__ float         g_X1[(size_t)N_NODES * DIM];   // fp32: streamed once in attend
__device__ __nv_bfloat16 g_X2b[(size_t)N_NODES * DIM];  // bf16: random-gathered (scores only)

typedef unsigned long long u64;

// ---- packed f32x2 helpers (sm_100) -------------------------------------------
__device__ __forceinline__ u64 pack_dup(float x) {
    u64 r;
    asm("mov.b64 %0, {%1, %1};" : "=l"(r) : "f"(x));
    return r;
}
__device__ __forceinline__ void fma2(u64& d, u64 a, u64 b) {
    asm("fma.rn.f32x2 %0, %1, %2, %0;" : "+l"(d) : "l"(a), "l"(b));
}
__device__ __forceinline__ float2 unpack2(u64 v) {
    float2 f;
    asm("mov.b64 {%0, %1}, %2;" : "=f"(f.x), "=f"(f.y) : "l"(v));
    return f;
}

// ---- cache-policy loads (createpolicy + cache_hint) ---------------------------
__device__ __forceinline__ u64 make_evict_last_policy() {
    u64 pol;
    asm("createpolicy.fractional.L2::evict_last.b64 %0, 1.0;" : "=l"(pol));
    return pol;
}
__device__ __forceinline__ float4 ldg_keep(const float* p, u64 pol) {
    float4 v;
    asm("ld.global.nc.L2::cache_hint.v4.f32 {%0,%1,%2,%3}, [%4], %5;"
        : "=f"(v.x), "=f"(v.y), "=f"(v.z), "=f"(v.w) : "l"(p), "l"(pol));
    return v;
}
__device__ __forceinline__ uint2 ldg_keep2(const void* p, u64 pol) {
    uint2 v;
    asm("ld.global.nc.L2::cache_hint.v2.b32 {%0,%1}, [%2], %3;"
        : "=r"(v.x), "=r"(v.y) : "l"(p), "l"(pol));
    return v;
}

// ---------------------------------------------------------------------------
// Kernel 1: GEMM  [100000 x 128] @ [128 x 128]  (x2 halves via blockIdx.y)
// BM=128, BN=128, BK=8, 256 threads, 8x8 per-thread tile as 8x4 f32x2 pairs.
// A tile stored PRE-DUPLICATED as u64 {a,a} pairs (kills 8 movs/k in mainloop).
// Half 0 -> g_X1 fp32 (+bias). Half 1 -> g_X2b bf16 (scores-only table).
// ---------------------------------------------------------------------------
#define BM 128
#define BN 128
#define BK 8

__global__ __launch_bounds__(256) void mlp1_gemm(const float* __restrict__ lat,
                                                 const float* __restrict__ W1,
                                                 const float* __restrict__ b1) {
    const int half = blockIdx.y;
    const float* __restrict__ B = W1 + (half ? (DIM * DIM) : 0); // row-major [256][128]
    const int m0 = blockIdx.x * BM;
    const u64 pol = make_evict_last_policy();

    __shared__ __align__(16) u64   As[2][BK][BM];   // duplicated-pair A tile (16 KB)
    __shared__ __align__(16) float Bs[2][BK][BN];   // 8 KB

    const int tid = threadIdx.x;            // 0..255
    const int tm  = (tid >> 4) * 8;         // 0..120
    const int tn  = (tid & 15) * 8;         // 0..120

    // A-load coords: one float4 per thread per stage.
    const int la_m  = tid >> 1;              // 0..127
    const int la_kq = (tid & 1) * 4;         // 0 or 4
    int la_gm = m0 + la_m;
    if (la_gm >= N_NODES) la_gm = N_NODES - 1;   // clamp (stores are guarded)
    const float* la_ptr = lat + (size_t)la_gm * DIM + la_kq;

    // B-load coords: one float4 per thread per stage.
    const int lb_k = tid >> 5;               // 0..7
    const int lb_c = (tid & 31) * 4;          // 0..124
    const float* lb_ptr = B + (size_t)lb_k * DIM + lb_c;

    u64 acc[8][4];
#pragma unroll
    for (int i = 0; i < 8; i++)
#pragma unroll
        for (int j = 0; j < 4; j++) acc[i][j] = 0ull;

    // Prefetch stage 0
    {
        float4 va = ldg_keep(la_ptr, pol);   // latents stay L2-resident for attend
        As[0][la_kq + 0][la_m] = pack_dup(va.x);
        As[0][la_kq + 1][la_m] = pack_dup(va.y);
        As[0][la_kq + 2][la_m] = pack_dup(va.z);
        As[0][la_kq + 3][la_m] = pack_dup(va.w);
        *(float4*)(&Bs[0][lb_k][lb_c]) = *(const float4*)(lb_ptr);
    }
    __syncthreads();

    int s = 0;
    for (int k0 = 0; k0 < DIM; k0 += BK, s ^= 1) {
        const int nk0 = k0 + BK;
        if (nk0 < DIM) {
            float4 va = ldg_keep(la_ptr + nk0, pol);
            As[s ^ 1][la_kq + 0][la_m] = pack_dup(va.x);
            As[s ^ 1][la_kq + 1][la_m] = pack_dup(va.y);
            As[s ^ 1][la_kq + 2][la_m] = pack_dup(va.z);
            As[s ^ 1][la_kq + 3][la_m] = pack_dup(va.w);
            *(float4*)(&Bs[s ^ 1][lb_k][lb_c]) = *(const float4*)(lb_ptr + (size_t)nk0 * DIM);
        }

#pragma unroll
        for (int k = 0; k < BK; k++) {
            u64 a[8];
            {
                ulonglong2 t0 = *(const ulonglong2*)(&As[s][k][tm + 0]);
                ulonglong2 t1 = *(const ulonglong2*)(&As[s][k][tm + 2]);
                ulonglong2 t2 = *(const ulonglong2*)(&As[s][k][tm + 4]);
                ulonglong2 t3 = *(const ulonglong2*)(&As[s][k][tm + 6]);
                a[0] = t0.x; a[1] = t0.y; a[2] = t1.x; a[3] = t1.y;
                a[4] = t2.x; a[5] = t2.y; a[6] = t3.x; a[7] = t3.y;
            }
            ulonglong2 bv0 = *(const ulonglong2*)(&Bs[s][k][tn]);
            ulonglong2 bv1 = *(const ulonglong2*)(&Bs[s][k][tn + 4]);
            u64 b0 = bv0.x, b1 = bv0.y, b2 = bv1.x, b3 = bv1.y;
#pragma unroll
            for (int i = 0; i < 8; i++) {
                fma2(acc[i][0], a[i], b0);
                fma2(acc[i][1], a[i], b1);
                fma2(acc[i][2], a[i], b2);
                fma2(acc[i][3], a[i], b3);
            }
        }
        __syncthreads();
    }

    // Epilogue.
    if (half == 0) {
        // X1 fp32 with bias.
        float bias[8];
#pragma unroll
        for (int j = 0; j < 8; j++) bias[j] = b1[tn + j];
#pragma unroll
        for (int i = 0; i < 8; i++) {
            const int gm = m0 + tm + i;
            if (gm < N_NODES) {
                float2 p0 = unpack2(acc[i][0]);
                float2 p1 = unpack2(acc[i][1]);
                float2 p2 = unpack2(acc[i][2]);
                float2 p3 = unpack2(acc[i][3]);
                float4 v0, v1;
                v0.x = p0.x + bias[0];
                v0.y = p0.y + bias[1];
                v0.z = p1.x + bias[2];
                v0.w = p1.y + bias[3];
                v1.x = p2.x + bias[4];
                v1.y = p2.y + bias[5];
                v1.z = p3.x + bias[6];
                v1.w = p3.y + bias[7];
                float* o = g_X1 + (size_t)gm * DIM + tn;
                *(float4*)(o)     = v0;
                *(float4*)(o + 4) = v1;
            }
        }
    } else {
        // X2 bf16 (no bias: b1 belongs to the central half only... it is added
        // once to X1; score uses relu(X1 + X2) so the sum carries it).
#pragma unroll
        for (int i = 0; i < 8; i++) {
            const int gm = m0 + tm + i;
            if (gm < N_NODES) {
                float2 p0 = unpack2(acc[i][0]);
                float2 p1 = unpack2(acc[i][1]);
                float2 p2 = unpack2(acc[i][2]);
                float2 p3 = unpack2(acc[i][3]);
                __nv_bfloat162 h0 = __floats2bfloat162_rn(p0.x, p0.y);
                __nv_bfloat162 h1 = __floats2bfloat162_rn(p1.x, p1.y);
                __nv_bfloat162 h2 = __floats2bfloat162_rn(p2.x, p2.y);
                __nv_bfloat162 h3 = __floats2bfloat162_rn(p3.x, p3.y);
                uint4 v;
                v.x = *(uint32_t*)&h0;
                v.y = *(uint32_t*)&h1;
                v.z = *(uint32_t*)&h2;
                v.w = *(uint32_t*)&h3;
                *(uint4*)((uint32_t*)g_X2b + (size_t)gm * (DIM / 2) + (tn >> 1)) = v;
            }
        }
    }
}

// ---------------------------------------------------------------------------
// Kernel 2: fused gather / score / softmax / weighted sum. One warp per node.
// Single-pass paired gathers (X2b[j] + latents[j] in one reuse window).
// X2 gathered as bf16 (halves score-gather L2 bytes); latents fp32 for output.
// ---------------------------------------------------------------------------
__global__ __launch_bounds__(256) void attend_kernel(const float* __restrict__ lat,
                                                     const int* __restrict__ nbr,
                                                     const float* __restrict__ W2,
                                                     float* __restrict__ out) {
    __shared__ float s_w2[DIM];
    const int tid = threadIdx.x;
    if (tid < DIM) s_w2[tid] = W2[tid];
    __syncthreads();

    const int n = blockIdx.x * (blockDim.x >> 5) + (tid >> 5);
    if (n >= N_NODES) return;
    const int lane = tid & 31;
    const u64 pol = make_evict_last_policy();

    const float4 x1  = __ldcs((const float4*)(g_X1 + (size_t)n * DIM + lane * 4));
    const float4 w2v = *(const float4*)(s_w2 + lane * 4);

    int js[KNB];
    {
        const int4* p = (const int4*)(nbr + (size_t)n * KNB);
#pragma unroll
        for (int q = 0; q < 4; q++) {
            int4 v = __ldcs(p + q);
            js[q * 4 + 0] = v.x;
            js[q * 4 + 1] = v.y;
            js[q * 4 + 2] = v.z;
            js[q * 4 + 3] = v.w;
        }
    }

    float  sc[KNB];
    float4 lb[KNB];
#pragma unroll
    for (int k = 0; k < KNB; k++) {
        const size_t roff = (size_t)js[k] * DIM;
        const uint2  u  = ldg_keep2(g_X2b + roff + lane * 4, pol);   // 4 bf16
        const float4 lv = ldg_keep(lat + roff + lane * 4, pol);
        lb[k] = lv;
        const float2 f0 = __bfloat1622float2(*(const __nv_bfloat162*)&u.x);
        const float2 f1 = __bfloat1622float2(*(const __nv_bfloat162*)&u.y);
        float p = fmaxf(x1.x + f0.x, 0.f) * w2v.x;
        p = fmaf(fmaxf(x1.y + f0.y, 0.f), w2v.y, p);
        p = fmaf(fmaxf(x1.z + f1.x, 0.f), w2v.z, p);
        p = fmaf(fmaxf(x1.w + f1.y, 0.f), w2v.w, p);
        sc[k] = p;
    }

    // Warp-reduce each of the 16 scores (result identical in all lanes).
#pragma unroll
    for (int k = 0; k < KNB; k++) {
        float p = sc[k];
        p += __shfl_xor_sync(0xffffffffu, p, 16);
        p += __shfl_xor_sync(0xffffffffu, p, 8);
        p += __shfl_xor_sync(0xffffffffu, p, 4);
        p += __shfl_xor_sync(0xffffffffu, p, 2);
        p += __shfl_xor_sync(0xffffffffu, p, 1);
        sc[k] = p;
    }

    // Softmax over K=16 (b2 cancels).
    float m = sc[0];
#pragma unroll
    for (int k = 1; k < KNB; k++) m = fmaxf(m, sc[k]);
    float ssum = 0.f;
#pragma unroll
    for (int k = 0; k < KNB; k++) {
        sc[k] = __expf(sc[k] - m);
        ssum += sc[k];
    }
    const float inv = 1.f / ssum;

    float4 acc = make_float4(0.f, 0.f, 0.f, 0.f);
#pragma unroll
    for (int k = 0; k < KNB; k++) {
        const float w = sc[k] * inv;
        acc.x = fmaf(w, lb[k].x, acc.x);
        acc.y = fmaf(w, lb[k].y, acc.y);
        acc.z = fmaf(w, lb[k].z, acc.z);
        acc.w = fmaf(w, lb[k].w, acc.w);
    }
    __stcs((float4*)(out + (size_t)n * DIM + lane * 4), acc);
}

// ---------------------------------------------------------------------------
// Launch
// ---------------------------------------------------------------------------
extern "C" void kernel_launch(void* const* d_in, const int* in_sizes, int n_in,
                              void* d_out, int out_size) {
    const float* latents   = (const float*)d_in[0];
    const int*   neighbors = (const int*)d_in[1];   // int32 (JAX x64-disabled)
    const float* W1        = (const float*)d_in[2];
    const float* b1        = (const float*)d_in[3];
    const float* W2        = (const float*)d_in[4];
    // d_in[5] = b2: cancels in softmax.
    float* out = (float*)d_out;

    (void)in_sizes; (void)n_in; (void)out_size;

    dim3 ggrid((N_NODES + BM - 1) / BM, 2);
    mlp1_gemm<<<ggrid, 256>>>(latents, W1, b1);

    const int warps_per_block = 8;
    const int blocks = (N_NODES + warps_per_block - 1) / warps_per_block;
    attend_kernel<<<blocks, warps_per_block * 32>>>(latents, neighbors, W2, out);
}

// round 8
// speedup vs baseline: 1.3044x; 1.0701x over previous
#include <cuda_runtime.h>
#include <cuda_bf16.h>
#include <cstdint>

#define N_NODES 100000
#define DIM     128
#define KNB     16

// Scratch tables.
__device__ float         g_X1[(size_t)N_NODES * DIM];   // fp32: streamed once in attend
__device__ __nv_bfloat16 g_X2b[(size_t)N_NODES * DIM];  // bf16: random-gathered (scores only)

typedef unsigned long long u64;

// ---- packed f32x2 helpers (sm_100) -------------------------------------------
__device__ __forceinline__ u64 pack_dup(float x) {
    u64 r;
    asm("mov.b64 %0, {%1, %1};" : "=l"(r) : "f"(x));
    return r;
}
__device__ __forceinline__ void fma2(u64& d, u64 a, u64 b) {
    asm("fma.rn.f32x2 %0, %1, %2, %0;" : "+l"(d) : "l"(a), "l"(b));
}
__device__ __forceinline__ float2 unpack2(u64 v) {
    float2 f;
    asm("mov.b64 {%0, %1}, %2;" : "=f"(f.x), "=f"(f.y) : "l"(v));
    return f;
}

// ---- cache-policy loads (createpolicy + cache_hint) ---------------------------
__device__ __forceinline__ u64 make_evict_last_policy() {
    u64 pol;
    asm("createpolicy.fractional.L2::evict_last.b64 %0, 1.0;" : "=l"(pol));
    return pol;
}
__device__ __forceinline__ float4 ldg_keep(const float* p, u64 pol) {
    float4 v;
    asm("ld.global.nc.L2::cache_hint.v4.f32 {%0,%1,%2,%3}, [%4], %5;"
        : "=f"(v.x), "=f"(v.y), "=f"(v.z), "=f"(v.w) : "l"(p), "l"(pol));
    return v;
}
__device__ __forceinline__ uint2 ldg_keep2(const void* p, u64 pol) {
    uint2 v;
    asm("ld.global.nc.L2::cache_hint.v2.b32 {%0,%1}, [%2], %3;"
        : "=r"(v.x), "=r"(v.y) : "l"(p), "l"(pol));
    return v;
}

// ---------------------------------------------------------------------------
// Kernel 1: GEMM  [100000 x 128] @ [128 x 128]  (x2 halves via blockIdx.y)
// BM=128, BN=128, BK=8, 256 threads (2 blocks/SM forced), 8x8 per-thread tile
// as 8x4 f32x2 pairs, double-buffered smem, mov-dup in mainloop (R5 form).
// Half 0 -> g_X1 fp32 (+bias). Half 1 -> g_X2b bf16.
// ---------------------------------------------------------------------------
#define BM 128
#define BN 128
#define BK 8

__global__ __launch_bounds__(256, 2) void mlp1_gemm(const float* __restrict__ lat,
                                                    const float* __restrict__ W1,
                                                    const float* __restrict__ b1) {
    const int half = blockIdx.y;
    const float* __restrict__ B = W1 + (half ? (DIM * DIM) : 0); // row-major [256][128]
    const int m0 = blockIdx.x * BM;
    const u64 pol = make_evict_last_policy();

    __shared__ __align__(16) float As[2][BK][BM + 4]; // transposed A tile, padded
    __shared__ __align__(16) float Bs[2][BK][BN];

    const int tid = threadIdx.x;            // 0..255
    const int tm  = (tid >> 4) * 8;         // 0..120
    const int tn  = (tid & 15) * 8;         // 0..120

    // A-load coords: one float4 per thread per stage.
    const int la_m  = tid >> 1;              // 0..127
    const int la_kq = (tid & 1) * 4;         // 0 or 4
    int la_gm = m0 + la_m;
    if (la_gm >= N_NODES) la_gm = N_NODES - 1;   // clamp (stores are guarded)
    const float* la_ptr = lat + (size_t)la_gm * DIM + la_kq;

    // B-load coords: one float4 per thread per stage.
    const int lb_k = tid >> 5;               // 0..7
    const int lb_c = (tid & 31) * 4;          // 0..124
    const float* lb_ptr = B + (size_t)lb_k * DIM + lb_c;

    u64 acc[8][4];
#pragma unroll
    for (int i = 0; i < 8; i++)
#pragma unroll
        for (int j = 0; j < 4; j++) acc[i][j] = 0ull;

    // Prefetch stage 0
    {
        float4 va = ldg_keep(la_ptr, pol);   // latents stay L2-resident for attend
        As[0][la_kq + 0][la_m] = va.x;
        As[0][la_kq + 1][la_m] = va.y;
        As[0][la_kq + 2][la_m] = va.z;
        As[0][la_kq + 3][la_m] = va.w;
        *(float4*)(&Bs[0][lb_k][lb_c]) = *(const float4*)(lb_ptr);
    }
    __syncthreads();

    int s = 0;
    for (int k0 = 0; k0 < DIM; k0 += BK, s ^= 1) {
        const int nk0 = k0 + BK;
        if (nk0 < DIM) {
            float4 va = ldg_keep(la_ptr + nk0, pol);
            As[s ^ 1][la_kq + 0][la_m] = va.x;
            As[s ^ 1][la_kq + 1][la_m] = va.y;
            As[s ^ 1][la_kq + 2][la_m] = va.z;
            As[s ^ 1][la_kq + 3][la_m] = va.w;
            *(float4*)(&Bs[s ^ 1][lb_k][lb_c]) = *(const float4*)(lb_ptr + (size_t)nk0 * DIM);
        }

#pragma unroll
        for (int k = 0; k < BK; k++) {
            float a[8];
            *(float4*)(a)     = *(const float4*)(&As[s][k][tm]);
            *(float4*)(a + 4) = *(const float4*)(&As[s][k][tm + 4]);
            ulonglong2 bv0 = *(const ulonglong2*)(&Bs[s][k][tn]);
            ulonglong2 bv1 = *(const ulonglong2*)(&Bs[s][k][tn + 4]);
            u64 b0 = bv0.x, b1 = bv0.y, b2 = bv1.x, b3 = bv1.y;
#pragma unroll
            for (int i = 0; i < 8; i++) {
                u64 ad = pack_dup(a[i]);
                fma2(acc[i][0], ad, b0);
                fma2(acc[i][1], ad, b1);
                fma2(acc[i][2], ad, b2);
                fma2(acc[i][3], ad, b3);
            }
        }
        __syncthreads();
    }

    // Epilogue.
    if (half == 0) {
        float bias[8];
#pragma unroll
        for (int j = 0; j < 8; j++) bias[j] = b1[tn + j];
#pragma unroll
        for (int i = 0; i < 8; i++) {
            const int gm = m0 + tm + i;
            if (gm < N_NODES) {
                float2 p0 = unpack2(acc[i][0]);
                float2 p1 = unpack2(acc[i][1]);
                float2 p2 = unpack2(acc[i][2]);
                float2 p3 = unpack2(acc[i][3]);
                float4 v0, v1;
                v0.x = p0.x + bias[0];
                v0.y = p0.y + bias[1];
                v0.z = p1.x + bias[2];
                v0.w = p1.y + bias[3];
                v1.x = p2.x + bias[4];
                v1.y = p2.y + bias[5];
                v1.z = p3.x + bias[6];
                v1.w = p3.y + bias[7];
                float* o = g_X1 + (size_t)gm * DIM + tn;
                *(float4*)(o)     = v0;
                *(float4*)(o + 4) = v1;
            }
        }
    } else {
        // X2 -> bf16 table (scores only).
#pragma unroll
        for (int i = 0; i < 8; i++) {
            const int gm = m0 + tm + i;
            if (gm < N_NODES) {
                float2 p0 = unpack2(acc[i][0]);
                float2 p1 = unpack2(acc[i][1]);
                float2 p2 = unpack2(acc[i][2]);
                float2 p3 = unpack2(acc[i][3]);
                __nv_bfloat162 h0 = __floats2bfloat162_rn(p0.x, p0.y);
                __nv_bfloat162 h1 = __floats2bfloat162_rn(p1.x, p1.y);
                __nv_bfloat162 h2 = __floats2bfloat162_rn(p2.x, p2.y);
                __nv_bfloat162 h3 = __floats2bfloat162_rn(p3.x, p3.y);
                uint4 v;
                v.x = *(uint32_t*)&h0;
                v.y = *(uint32_t*)&h1;
                v.z = *(uint32_t*)&h2;
                v.w = *(uint32_t*)&h3;
                *(uint4*)((uint32_t*)g_X2b + (size_t)gm * (DIM / 2) + (tn >> 1)) = v;
            }
        }
    }
}

// ---------------------------------------------------------------------------
// Kernel 2: fused gather / score / softmax / weighted sum. One warp per node.
// TWO-PASS, low-register: pass1 gathers bf16 X2 for scores; pass2 re-gathers
// fp32 latents for the weighted sum. Both tables (76 MB) are L2-resident
// (evict_last), so the second touch hits L2 — no R3-style DRAM doubling.
// 128-thread blocks for fine occupancy granularity.
// ---------------------------------------------------------------------------
__global__ __launch_bounds__(128) void attend_kernel(const float* __restrict__ lat,
                                                     const int* __restrict__ nbr,
                                                     const float* __restrict__ W2,
                                                     float* __restrict__ out) {
    __shared__ float s_w2[DIM];
    const int tid = threadIdx.x;
    s_w2[tid] = W2[tid];
    __syncthreads();

    const int n = blockIdx.x * 4 + (tid >> 5);
    if (n >= N_NODES) return;
    const int lane = tid & 31;
    const u64 pol = make_evict_last_policy();

    const float4 x1  = __ldcs((const float4*)(g_X1 + (size_t)n * DIM + lane * 4));
    const float4 w2v = *(const float4*)(s_w2 + lane * 4);

    int js[KNB];
    {
        const int4* p = (const int4*)(nbr + (size_t)n * KNB);
#pragma unroll
        for (int q = 0; q < 4; q++) {
            int4 v = __ldcs(p + q);
            js[q * 4 + 0] = v.x;
            js[q * 4 + 1] = v.y;
            js[q * 4 + 2] = v.z;
            js[q * 4 + 3] = v.w;
        }
    }

    // Pass 1: scores from bf16 X2 gather (8 B/lane/neighbor).
    float sc[KNB];
#pragma unroll
    for (int k = 0; k < KNB; k++) {
        const uint2 u = ldg_keep2(g_X2b + (size_t)js[k] * DIM + lane * 4, pol);
        const float2 f0 = __bfloat1622float2(*(const __nv_bfloat162*)&u.x);
        const float2 f1 = __bfloat1622float2(*(const __nv_bfloat162*)&u.y);
        float p = fmaxf(x1.x + f0.x, 0.f) * w2v.x;
        p = fmaf(fmaxf(x1.y + f0.y, 0.f), w2v.y, p);
        p = fmaf(fmaxf(x1.z + f1.x, 0.f), w2v.z, p);
        p = fmaf(fmaxf(x1.w + f1.y, 0.f), w2v.w, p);
        sc[k] = p;
    }

    // Warp-reduce each of the 16 scores (result identical in all lanes).
#pragma unroll
    for (int k = 0; k < KNB; k++) {
        float p = sc[k];
        p += __shfl_xor_sync(0xffffffffu, p, 16);
        p += __shfl_xor_sync(0xffffffffu, p, 8);
        p += __shfl_xor_sync(0xffffffffu, p, 4);
        p += __shfl_xor_sync(0xffffffffu, p, 2);
        p += __shfl_xor_sync(0xffffffffu, p, 1);
        sc[k] = p;
    }

    // Softmax over K=16 (b2 cancels).
    float m = sc[0];
#pragma unroll
    for (int k = 1; k < KNB; k++) m = fmaxf(m, sc[k]);
    float ssum = 0.f;
#pragma unroll
    for (int k = 0; k < KNB; k++) {
        sc[k] = __expf(sc[k] - m);
        ssum += sc[k];
    }
    const float inv = 1.f / ssum;

    // Pass 2: weighted sum over fp32 latents (L2-resident re-gather).
    float4 acc = make_float4(0.f, 0.f, 0.f, 0.f);
#pragma unroll 4
    for (int k = 0; k < KNB; k++) {
        const float4 lv = ldg_keep(lat + (size_t)js[k] * DIM + lane * 4, pol);
        const float w = sc[k] * inv;
        acc.x = fmaf(w, lv.x, acc.x);
        acc.y = fmaf(w, lv.y, acc.y);
        acc.z = fmaf(w, lv.z, acc.z);
        acc.w = fmaf(w, lv.w, acc.w);
    }
    __stcs((float4*)(out + (size_t)n * DIM + lane * 4), acc);
}

// ---------------------------------------------------------------------------
// Launch
// ---------------------------------------------------------------------------
extern "C" void kernel_launch(void* const* d_in, const int* in_sizes, int n_in,
                              void* d_out, int out_size) {
    const float* latents   = (const float*)d_in[0];
    const int*   neighbors = (const int*)d_in[1];   // int32 (JAX x64-disabled)
    const float* W1        = (const float*)d_in[2];
    const float* b1        = (const float*)d_in[3];
    const float* W2        = (const float*)d_in[4];
    // d_in[5] = b2: cancels in softmax.
    float* out = (float*)d_out;

    (void)in_sizes; (void)n_in; (void)out_size;

    dim3 ggrid((N_NODES + BM - 1) / BM, 2);
    mlp1_gemm<<<ggrid, 256>>>(latents, W1, b1);

    const int blocks = (N_NODES + 3) / 4;   // 4 warps (nodes) per 128-thread block
    attend_kernel<<<blocks, 128>>>(latents, neighbors, W2, out);
}

// round 9
// speedup vs baseline: 1.3853x; 1.0620x over previous
#include <cuda_runtime.h>
#include <cuda_bf16.h>
#include <cstdint>

#define N_NODES 100000
#define DIM     128
#define KNB     16

// Scratch tables.
__device__ float         g_X1[(size_t)N_NODES * DIM];   // fp32: streamed once in attend
__device__ __nv_bfloat16 g_X2b[(size_t)N_NODES * DIM];  // bf16: random-gathered (scores only)

typedef unsigned long long u64;

// ---- packed f32x2 helpers (sm_100) -------------------------------------------
__device__ __forceinline__ u64 pack_dup(float x) {
    u64 r;
    asm("mov.b64 %0, {%1, %1};" : "=l"(r) : "f"(x));
    return r;
}
__device__ __forceinline__ void fma2(u64& d, u64 a, u64 b) {
    asm("fma.rn.f32x2 %0, %1, %2, %0;" : "+l"(d) : "l"(a), "l"(b));
}
__device__ __forceinline__ float2 unpack2(u64 v) {
    float2 f;
    asm("mov.b64 {%0, %1}, %2;" : "=f"(f.x), "=f"(f.y) : "l"(v));
    return f;
}

// ---- cache-policy loads (createpolicy + cache_hint) ---------------------------
__device__ __forceinline__ u64 make_evict_last_policy() {
    u64 pol;
    asm("createpolicy.fractional.L2::evict_last.b64 %0, 1.0;" : "=l"(pol));
    return pol;
}
__device__ __forceinline__ float4 ldg_keep(const float* p, u64 pol) {
    float4 v;
    asm("ld.global.nc.L2::cache_hint.v4.f32 {%0,%1,%2,%3}, [%4], %5;"
        : "=f"(v.x), "=f"(v.y), "=f"(v.z), "=f"(v.w) : "l"(p), "l"(pol));
    return v;
}
__device__ __forceinline__ uint2 ldg_keep2(const void* p, u64 pol) {
    uint2 v;
    asm("ld.global.nc.L2::cache_hint.v2.b32 {%0,%1}, [%2], %3;"
        : "=r"(v.x), "=r"(v.y) : "l"(p), "l"(pol));
    return v;
}

// ---------------------------------------------------------------------------
// Kernel 1: GEMM  [100000 x 128] @ [128 x 128]  (x2 halves via blockIdx.y)
// BM=128, BN=128, BK=16, 256 threads (2 blocks/SM), 8x8 per-thread tile as
// 8x4 f32x2 pairs, double-buffered smem. 8 stages (half the syncs of BK=8).
// Half 0 -> g_X1 fp32 (+bias). Half 1 -> g_X2b bf16.
// ---------------------------------------------------------------------------
#define BM 128
#define BN 128
#define BK 16

__global__ __launch_bounds__(256, 2) void mlp1_gemm(const float* __restrict__ lat,
                                                    const float* __restrict__ W1,
                                                    const float* __restrict__ b1) {
    const int half = blockIdx.y;
    const float* __restrict__ B = W1 + (half ? (DIM * DIM) : 0); // row-major [256][128]
    const int m0 = blockIdx.x * BM;
    const u64 pol = make_evict_last_policy();

    __shared__ __align__(16) float As[2][BK][BM + 4]; // transposed A tile, padded
    __shared__ __align__(16) float Bs[2][BK][BN];

    const int tid = threadIdx.x;            // 0..255
    const int tm  = (tid >> 4) * 8;         // 0..120
    const int tn  = (tid & 15) * 8;         // 0..120

    // A-load coords: two float4 per thread per stage (512 float4 total).
    // f = tid*2+t: m = f>>2 (0..127), kq = (f&3)*4 (0,4,8,12).
    const int la_m  = tid >> 1;              // 0..127
    int la_gm = m0 + la_m;
    if (la_gm >= N_NODES) la_gm = N_NODES - 1;   // clamp (stores are guarded)
    const float* la_ptr = lat + (size_t)la_gm * DIM;

    // B-load coords: two float4 per thread per stage.
    const float* lb_ptr = B;

    u64 acc[8][4];
#pragma unroll
    for (int i = 0; i < 8; i++)
#pragma unroll
        for (int j = 0; j < 4; j++) acc[i][j] = 0ull;

    // Stage loader: loads A[BMxBK] transposed + B[BKxBN] for k-offset k0 into buf.
    auto load_stage = [&](int buf, int k0) {
#pragma unroll
        for (int t = 0; t < 2; t++) {
            int f  = tid * 2 + t;            // 0..511
            int m  = f >> 2;                 // 0..127  (la_m pairs with t via f)
            int kq = (f & 3) * 4;            // 0,4,8,12
            int gm = m0 + m;
            if (gm >= N_NODES) gm = N_NODES - 1;
            float4 v = ldg_keep(lat + (size_t)gm * DIM + k0 + kq, pol);
            As[buf][kq + 0][m] = v.x;
            As[buf][kq + 1][m] = v.y;
            As[buf][kq + 2][m] = v.z;
            As[buf][kq + 3][m] = v.w;
        }
#pragma unroll
        for (int t = 0; t < 2; t++) {
            int f  = tid * 2 + t;            // 0..511
            int kr = f >> 5;                 // 0..15
            int c  = (f & 31) * 4;           // 0..124
            *(float4*)(&Bs[buf][kr][c]) = *(const float4*)(lb_ptr + (size_t)(k0 + kr) * DIM + c);
        }
    };

    load_stage(0, 0);
    __syncthreads();

    int s = 0;
    for (int k0 = 0; k0 < DIM; k0 += BK, s ^= 1) {
        const int nk0 = k0 + BK;
        if (nk0 < DIM) load_stage(s ^ 1, nk0);

#pragma unroll
        for (int k = 0; k < BK; k++) {
            float a[8];
            *(float4*)(a)     = *(const float4*)(&As[s][k][tm]);
            *(float4*)(a + 4) = *(const float4*)(&As[s][k][tm + 4]);
            ulonglong2 bv0 = *(const ulonglong2*)(&Bs[s][k][tn]);
            ulonglong2 bv1 = *(const ulonglong2*)(&Bs[s][k][tn + 4]);
            u64 b0 = bv0.x, b1 = bv0.y, b2 = bv1.x, b3 = bv1.y;
#pragma unroll
            for (int i = 0; i < 8; i++) {
                u64 ad = pack_dup(a[i]);
                fma2(acc[i][0], ad, b0);
                fma2(acc[i][1], ad, b1);
                fma2(acc[i][2], ad, b2);
                fma2(acc[i][3], ad, b3);
            }
        }
        __syncthreads();
    }

    // Epilogue.
    if (half == 0) {
        float bias[8];
#pragma unroll
        for (int j = 0; j < 8; j++) bias[j] = b1[tn + j];
#pragma unroll
        for (int i = 0; i < 8; i++) {
            const int gm = m0 + tm + i;
            if (gm < N_NODES) {
                float2 p0 = unpack2(acc[i][0]);
                float2 p1 = unpack2(acc[i][1]);
                float2 p2 = unpack2(acc[i][2]);
                float2 p3 = unpack2(acc[i][3]);
                float4 v0, v1;
                v0.x = p0.x + bias[0];
                v0.y = p0.y + bias[1];
                v0.z = p1.x + bias[2];
                v0.w = p1.y + bias[3];
                v1.x = p2.x + bias[4];
                v1.y = p2.y + bias[5];
                v1.z = p3.x + bias[6];
                v1.w = p3.y + bias[7];
                float* o = g_X1 + (size_t)gm * DIM + tn;
                *(float4*)(o)     = v0;
                *(float4*)(o + 4) = v1;
            }
        }
    } else {
        // X2 -> bf16 table (scores only).
#pragma unroll
        for (int i = 0; i < 8; i++) {
            const int gm = m0 + tm + i;
            if (gm < N_NODES) {
                float2 p0 = unpack2(acc[i][0]);
                float2 p1 = unpack2(acc[i][1]);
                float2 p2 = unpack2(acc[i][2]);
                float2 p3 = unpack2(acc[i][3]);
                __nv_bfloat162 h0 = __floats2bfloat162_rn(p0.x, p0.y);
                __nv_bfloat162 h1 = __floats2bfloat162_rn(p1.x, p1.y);
                __nv_bfloat162 h2 = __floats2bfloat162_rn(p2.x, p2.y);
                __nv_bfloat162 h3 = __floats2bfloat162_rn(p3.x, p3.y);
                uint4 v;
                v.x = *(uint32_t*)&h0;
                v.y = *(uint32_t*)&h1;
                v.z = *(uint32_t*)&h2;
                v.w = *(uint32_t*)&h3;
                *(uint4*)((uint32_t*)g_X2b + (size_t)gm * (DIM / 2) + (tn >> 1)) = v;
            }
        }
    }
}

// ---------------------------------------------------------------------------
// Kernel 2: fused gather / score / ONLINE-softmax / weighted sum.
// One warp per node. Single-pass (x2b[j] + lat[j] gathered together) AND
// buffer-free: flash-style running (max, sum, acc) — no lb[16], ~60 regs.
// Groups of 4 neighbors for load ILP.
// ---------------------------------------------------------------------------
__global__ __launch_bounds__(128) void attend_kernel(const float* __restrict__ lat,
                                                     const int* __restrict__ nbr,
                                                     const float* __restrict__ W2,
                                                     float* __restrict__ out) {
    __shared__ float s_w2[DIM];
    const int tid = threadIdx.x;
    s_w2[tid] = W2[tid];
    __syncthreads();

    const int n = blockIdx.x * 4 + (tid >> 5);
    if (n >= N_NODES) return;
    const int lane = tid & 31;
    const u64 pol = make_evict_last_policy();

    const float4 x1  = __ldcs((const float4*)(g_X1 + (size_t)n * DIM + lane * 4));
    const float4 w2v = *(const float4*)(s_w2 + lane * 4);

    int js[KNB];
    {
        const int4* p = (const int4*)(nbr + (size_t)n * KNB);
#pragma unroll
        for (int q = 0; q < 4; q++) {
            int4 v = __ldcs(p + q);
            js[q * 4 + 0] = v.x;
            js[q * 4 + 1] = v.y;
            js[q * 4 + 2] = v.z;
            js[q * 4 + 3] = v.w;
        }
    }

    float  rm = -__int_as_float(0x7f800000);  // running max = -inf
    float  rz = 0.f;                          // running sum
    float4 acc = make_float4(0.f, 0.f, 0.f, 0.f);

#pragma unroll
    for (int g = 0; g < 4; g++) {
        // Issue all 8 loads of the group up front (paired per-row gathers).
        uint2  u[4];
        float4 lv[4];
#pragma unroll
        for (int t = 0; t < 4; t++) {
            const size_t roff = (size_t)js[g * 4 + t] * DIM + lane * 4;
            u[t]  = ldg_keep2(g_X2b + roff, pol);
            lv[t] = ldg_keep(lat + roff, pol);
        }

        // Per-lane partial scores.
        float p[4];
#pragma unroll
        for (int t = 0; t < 4; t++) {
            const float2 f0 = __bfloat1622float2(*(const __nv_bfloat162*)&u[t].x);
            const float2 f1 = __bfloat1622float2(*(const __nv_bfloat162*)&u[t].y);
            float q = fmaxf(x1.x + f0.x, 0.f) * w2v.x;
            q = fmaf(fmaxf(x1.y + f0.y, 0.f), w2v.y, q);
            q = fmaf(fmaxf(x1.z + f1.x, 0.f), w2v.z, q);
            q = fmaf(fmaxf(x1.w + f1.y, 0.f), w2v.w, q);
            p[t] = q;
        }
        // Warp-reduce the 4 scores (interleaved for shfl ILP).
#pragma unroll
        for (int d = 16; d > 0; d >>= 1) {
            p[0] += __shfl_xor_sync(0xffffffffu, p[0], d);
            p[1] += __shfl_xor_sync(0xffffffffu, p[1], d);
            p[2] += __shfl_xor_sync(0xffffffffu, p[2], d);
            p[3] += __shfl_xor_sync(0xffffffffu, p[3], d);
        }
        // Online-softmax update with the 4 rows (lv still live).
#pragma unroll
        for (int t = 0; t < 4; t++) {
            const float s  = p[t];
            const float mn = fmaxf(rm, s);
            const float f  = __expf(rm - mn);   // exp(-inf)=0 on first item
            const float e  = __expf(s - mn);
            rm = mn;
            rz = fmaf(rz, f, e);
            acc.x = fmaf(acc.x, f, e * lv[t].x);
            acc.y = fmaf(acc.y, f, e * lv[t].y);
            acc.z = fmaf(acc.z, f, e * lv[t].z);
            acc.w = fmaf(acc.w, f, e * lv[t].w);
        }
    }

    const float inv = 1.f / rz;
    float4 o;
    o.x = acc.x * inv;
    o.y = acc.y * inv;
    o.z = acc.z * inv;
    o.w = acc.w * inv;
    __stcs((float4*)(out + (size_t)n * DIM + lane * 4), o);
}

// ---------------------------------------------------------------------------
// Launch
// ---------------------------------------------------------------------------
extern "C" void kernel_launch(void* const* d_in, const int* in_sizes, int n_in,
                              void* d_out, int out_size) {
    const float* latents   = (const float*)d_in[0];
    const int*   neighbors = (const int*)d_in[1];   // int32 (JAX x64-disabled)
    const float* W1        = (const float*)d_in[2];
    const float* b1        = (const float*)d_in[3];
    const float* W2        = (const float*)d_in[4];
    // d_in[5] = b2: cancels in softmax.
    float* out = (float*)d_out;

    (void)in_sizes; (void)n_in; (void)out_size;

    dim3 ggrid((N_NODES + BM - 1) / BM, 2);
    mlp1_gemm<<<ggrid, 256>>>(latents, W1, b1);

    const int blocks = (N_NODES + 3) / 4;   // 4 warps (nodes) per 128-thread block
    attend_kernel<<<blocks, 128>>>(latents, neighbors, W2, out);
}

// round 10
// speedup vs baseline: 2.1279x; 1.5361x over previous
#include <cuda_runtime.h>
#include <cuda_bf16.h>
#include <cstdint>

#define N_NODES 100000
#define DIM     128
#define KNB     16

// Scratch tables.
__device__ float         g_X1[(size_t)N_NODES * DIM];   // fp32: streamed once in attend
__device__ __nv_bfloat16 g_X2b[(size_t)N_NODES * DIM];  // bf16: random-gathered (scores only)

typedef unsigned long long u64;

// ---- cache-policy loads (createpolicy + cache_hint) ---------------------------
__device__ __forceinline__ u64 make_evict_last_policy() {
    u64 pol;
    asm("createpolicy.fractional.L2::evict_last.b64 %0, 1.0;" : "=l"(pol));
    return pol;
}
__device__ __forceinline__ float4 ldg_keep(const float* p, u64 pol) {
    float4 v;
    asm("ld.global.nc.L2::cache_hint.v4.f32 {%0,%1,%2,%3}, [%4], %5;"
        : "=f"(v.x), "=f"(v.y), "=f"(v.z), "=f"(v.w) : "l"(p), "l"(pol));
    return v;
}
__device__ __forceinline__ uint2 ldg_keep2(const void* p, u64 pol) {
    uint2 v;
    asm("ld.global.nc.L2::cache_hint.v2.b32 {%0,%1}, [%2], %3;"
        : "=r"(v.x), "=r"(v.y) : "l"(p), "l"(pol));
    return v;
}

// ---- tf32 helpers --------------------------------------------------------------
__device__ __forceinline__ uint32_t f2tf32(float x) {
    uint32_t r;
    asm("cvt.rna.tf32.f32 %0, %1;" : "=r"(r) : "f"(x));
    return r;
}
__device__ __forceinline__ void mma_tf32(float* d, const uint32_t* a, const uint32_t* b) {
    asm volatile(
        "mma.sync.aligned.m16n8k8.row.col.f32.tf32.tf32.f32 "
        "{%0,%1,%2,%3}, {%4,%5,%6,%7}, {%8,%9}, {%0,%1,%2,%3};"
        : "+f"(d[0]), "+f"(d[1]), "+f"(d[2]), "+f"(d[3])
        : "r"(a[0]), "r"(a[1]), "r"(a[2]), "r"(a[3]), "r"(b[0]), "r"(b[1]));
}

// ---------------------------------------------------------------------------
// Kernel 1: tf32 tensor-core GEMM  [100000 x 128] @ [128 x 128] (x2 halves).
// CTA: 256 thr = 8 warps (2m x 4n), BM=128, BN=128, K staged 16, dbl-buffered.
// Warp tile 64x32 = 4x4 m16n8k8 tiles. Half 0 -> g_X1 fp32 (+b1); half 1 ->
// g_X2b bf16. Inputs cvt.rna.tf32 in the loaders.
// ---------------------------------------------------------------------------
#define GBK 16
#define APAD 20    // floats per A row (16 + 4) -> conflict-free frag reads
#define BPAD 136   // floats per B row (128 + 8)

__global__ __launch_bounds__(256, 2) void mlp1_gemm_mma(const float* __restrict__ lat,
                                                        const float* __restrict__ W1,
                                                        const float* __restrict__ b1) {
    const int half = blockIdx.y;
    const float* __restrict__ Bsrc = W1 + (half ? (DIM * DIM) : 0); // [128][128] row-major [k][n]
    const int m0 = blockIdx.x * 128;
    const u64 pol = make_evict_last_policy();

    __shared__ uint32_t Asm[2][128][APAD];   // [m][k] tf32, 20.0 KB
    __shared__ uint32_t Bsm[2][GBK][BPAD];   // [k][n] tf32, 17.0 KB
    __shared__ float    sb1[DIM];

    const int tid   = threadIdx.x;
    const int wid   = tid >> 5;
    const int lane  = tid & 31;
    const int warpm = (wid >> 2) * 64;   // 0 or 64
    const int warpn = (wid & 3) * 32;    // 0,32,64,96
    const int r     = lane >> 2;         // 0..7
    const int c     = lane & 3;          // 0..3

    if (tid < DIM) sb1[tid] = b1[tid];

    float acc[4][4][4];
#pragma unroll
    for (int tm = 0; tm < 4; tm++)
#pragma unroll
        for (int tn = 0; tn < 4; tn++)
#pragma unroll
            for (int q = 0; q < 4; q++) acc[tm][tn][q] = 0.f;

    // Stage loader: A[128m x 16k] + B[16k x 128n] at k-offset k0 into buf.
    auto load_stage = [&](int buf, int k0) {
#pragma unroll
        for (int i = 0; i < 2; i++) {           // A: 512 float4 / 256 thr
            int f   = i * 256 + tid;
            int row = f >> 2;                   // 0..127
            int cq  = (f & 3) * 4;              // 0,4,8,12
            int gm  = m0 + row;
            if (gm >= N_NODES) gm = N_NODES - 1;
            float4 v = ldg_keep(lat + (size_t)gm * DIM + k0 + cq, pol);
            uint4 t;
            t.x = f2tf32(v.x); t.y = f2tf32(v.y); t.z = f2tf32(v.z); t.w = f2tf32(v.w);
            *(uint4*)(&Asm[buf][row][cq]) = t;
        }
#pragma unroll
        for (int i = 0; i < 2; i++) {           // B: 512 float4 / 256 thr
            int f  = i * 256 + tid;
            int kr = f >> 5;                    // 0..15
            int cq = (f & 31) * 4;              // 0..124
            float4 v = *(const float4*)(Bsrc + (size_t)(k0 + kr) * DIM + cq);
            uint4 t;
            t.x = f2tf32(v.x); t.y = f2tf32(v.y); t.z = f2tf32(v.z); t.w = f2tf32(v.w);
            *(uint4*)(&Bsm[buf][kr][cq]) = t;
        }
    };

    load_stage(0, 0);
    __syncthreads();

    int s = 0;
    for (int k0 = 0; k0 < DIM; k0 += GBK, s ^= 1) {
        if (k0 + GBK < DIM) load_stage(s ^ 1, k0 + GBK);

#pragma unroll
        for (int ch = 0; ch < 2; ch++) {        // 2 chunks of k8 per stage
            const int kc = ch * 8;
            uint32_t af[4][4];
#pragma unroll
            for (int tm = 0; tm < 4; tm++) {
                const int mr = warpm + tm * 16;
                af[tm][0] = Asm[s][mr + r    ][kc + c];
                af[tm][1] = Asm[s][mr + r + 8][kc + c];
                af[tm][2] = Asm[s][mr + r    ][kc + c + 4];
                af[tm][3] = Asm[s][mr + r + 8][kc + c + 4];
            }
            uint32_t bf[4][2];
#pragma unroll
            for (int tn = 0; tn < 4; tn++) {
                const int nc = warpn + tn * 8;
                bf[tn][0] = Bsm[s][kc + c    ][nc + r];
                bf[tn][1] = Bsm[s][kc + c + 4][nc + r];
            }
#pragma unroll
            for (int tm = 0; tm < 4; tm++)
#pragma unroll
                for (int tn = 0; tn < 4; tn++)
                    mma_tf32(acc[tm][tn], af[tm], bf[tn]);
        }
        __syncthreads();
    }

    // Epilogue. C frag: c0,c1 @ (row=r, col=2c,2c+1); c2,c3 @ (row=r+8, same cols).
    if (half == 0) {
#pragma unroll
        for (int tm = 0; tm < 4; tm++) {
            const int gmA = m0 + warpm + tm * 16 + r;
            const int gmB = gmA + 8;
#pragma unroll
            for (int tn = 0; tn < 4; tn++) {
                const int nc = warpn + tn * 8 + 2 * c;
                const float bx = sb1[nc], by = sb1[nc + 1];
                if (gmA < N_NODES) {
                    float2 v = make_float2(acc[tm][tn][0] + bx, acc[tm][tn][1] + by);
                    *(float2*)(g_X1 + (size_t)gmA * DIM + nc) = v;
                }
                if (gmB < N_NODES) {
                    float2 v = make_float2(acc[tm][tn][2] + bx, acc[tm][tn][3] + by);
                    *(float2*)(g_X1 + (size_t)gmB * DIM + nc) = v;
                }
            }
        }
    } else {
#pragma unroll
        for (int tm = 0; tm < 4; tm++) {
            const int gmA = m0 + warpm + tm * 16 + r;
            const int gmB = gmA + 8;
#pragma unroll
            for (int tn = 0; tn < 4; tn++) {
                const int nc = warpn + tn * 8 + 2 * c;
                if (gmA < N_NODES) {
                    __nv_bfloat162 h = __floats2bfloat162_rn(acc[tm][tn][0], acc[tm][tn][1]);
                    ((uint32_t*)g_X2b)[(size_t)gmA * (DIM / 2) + (nc >> 1)] = *(uint32_t*)&h;
                }
                if (gmB < N_NODES) {
                    __nv_bfloat162 h = __floats2bfloat162_rn(acc[tm][tn][2], acc[tm][tn][3]);
                    ((uint32_t*)g_X2b)[(size_t)gmB * (DIM / 2) + (nc >> 1)] = *(uint32_t*)&h;
                }
            }
        }
    }
}

// ---------------------------------------------------------------------------
// Kernel 2: fused gather / score / ONLINE-softmax / weighted sum.
// One warp per node, single-pass paired gathers, flash-style running state.
// 32-bit gather address arithmetic (offsets < 2^31).
// ---------------------------------------------------------------------------
__global__ __launch_bounds__(128) void attend_kernel(const float* __restrict__ lat,
                                                     const int* __restrict__ nbr,
                                                     const float* __restrict__ W2,
                                                     float* __restrict__ out) {
    __shared__ float s_w2[DIM];
    const int tid = threadIdx.x;
    s_w2[tid] = W2[tid];
    __syncthreads();

    const int n = blockIdx.x * 4 + (tid >> 5);
    if (n >= N_NODES) return;
    const int lane = tid & 31;
    const u64 pol = make_evict_last_policy();

    const float4 x1  = __ldcs((const float4*)(g_X1 + (size_t)n * DIM + lane * 4));
    const float4 w2v = *(const float4*)(s_w2 + lane * 4);

    const char* latb = (const char*)lat;
    const char* x2b  = (const char*)g_X2b;
    const uint32_t lane16 = (uint32_t)lane << 4;
    const uint32_t lane8  = (uint32_t)lane << 3;

    int js[KNB];
    {
        const int4* p = (const int4*)(nbr + (size_t)n * KNB);
#pragma unroll
        for (int q = 0; q < 4; q++) {
            int4 v = __ldcs(p + q);
            js[q * 4 + 0] = v.x;
            js[q * 4 + 1] = v.y;
            js[q * 4 + 2] = v.z;
            js[q * 4 + 3] = v.w;
        }
    }

    float  rm = -__int_as_float(0x7f800000);  // running max = -inf
    float  rz = 0.f;                          // running sum
    float4 acc = make_float4(0.f, 0.f, 0.f, 0.f);

#pragma unroll
    for (int g = 0; g < 4; g++) {
        uint2  u[4];
        float4 lv[4];
#pragma unroll
        for (int t = 0; t < 4; t++) {
            const uint32_t ro = (uint32_t)js[g * 4 + t] << 9;      // row byte off (fp32)
            u[t]  = ldg_keep2(x2b + (ro >> 1) + lane8, pol);       // bf16 row
            lv[t] = ldg_keep((const float*)(latb + ro + lane16), pol);
        }

        float p[4];
#pragma unroll
        for (int t = 0; t < 4; t++) {
            const float2 f0 = __bfloat1622float2(*(const __nv_bfloat162*)&u[t].x);
            const float2 f1 = __bfloat1622float2(*(const __nv_bfloat162*)&u[t].y);
            float q = fmaxf(x1.x + f0.x, 0.f) * w2v.x;
            q = fmaf(fmaxf(x1.y + f0.y, 0.f), w2v.y, q);
            q = fmaf(fmaxf(x1.z + f1.x, 0.f), w2v.z, q);
            q = fmaf(fmaxf(x1.w + f1.y, 0.f), w2v.w, q);
            p[t] = q;
        }
#pragma unroll
        for (int d = 16; d > 0; d >>= 1) {
            p[0] += __shfl_xor_sync(0xffffffffu, p[0], d);
            p[1] += __shfl_xor_sync(0xffffffffu, p[1], d);
            p[2] += __shfl_xor_sync(0xffffffffu, p[2], d);
            p[3] += __shfl_xor_sync(0xffffffffu, p[3], d);
        }
#pragma unroll
        for (int t = 0; t < 4; t++) {
            const float sv = p[t];
            const float mn = fmaxf(rm, sv);
            const float f  = __expf(rm - mn);   // exp(-inf)=0 on first item
            const float e  = __expf(sv - mn);
            rm = mn;
            rz = fmaf(rz, f, e);
            acc.x = fmaf(acc.x, f, e * lv[t].x);
            acc.y = fmaf(acc.y, f, e * lv[t].y);
            acc.z = fmaf(acc.z, f, e * lv[t].z);
            acc.w = fmaf(acc.w, f, e * lv[t].w);
        }
    }

    const float inv = 1.f / rz;
    float4 o;
    o.x = acc.x * inv;
    o.y = acc.y * inv;
    o.z = acc.z * inv;
    o.w = acc.w * inv;
    __stcs((float4*)(out + (size_t)n * DIM + lane * 4), o);
}

// ---------------------------------------------------------------------------
// Launch
// ---------------------------------------------------------------------------
extern "C" void kernel_launch(void* const* d_in, const int* in_sizes, int n_in,
                              void* d_out, int out_size) {
    const float* latents   = (const float*)d_in[0];
    const int*   neighbors = (const int*)d_in[1];   // int32 (JAX x64-disabled)
    const float* W1        = (const float*)d_in[2];
    const float* b1        = (const float*)d_in[3];
    const float* W2        = (const float*)d_in[4];
    // d_in[5] = b2: cancels in softmax.
    float* out = (float*)d_out;

    (void)in_sizes; (void)n_in; (void)out_size;

    dim3 ggrid((N_NODES + 127) / 128, 2);
    mlp1_gemm_mma<<<ggrid, 256>>>(latents, W1, b1);

    const int blocks = (N_NODES + 3) / 4;   // 4 warps (nodes) per 128-thread block
    attend_kernel<<<blocks, 128>>>(latents, neighbors, W2, out);
}

// round 11
// speedup vs baseline: 2.2056x; 1.0365x over previous
#include <cuda_runtime.h>
#include <cuda_bf16.h>
#include <cuda_fp16.h>
#include <cstdint>

#define N_NODES 100000
#define DIM     128
#define KNB     16

// Scratch tables.
// g_X1: fp32, streamed once per node in attend.
__device__ float g_X1[(size_t)N_NODES * DIM];
// g_pair: fused gather table, 512 B per row. Per row j, lane l (0..31) owns
// 16 bytes at offset l*16: [4 x bf16 X2 dims 4l..4l+3 | 4 x fp16 lat dims 4l..4l+3].
// One LDG.128 per neighbor per lane serves BOTH the score and the weighted sum.
__device__ uint32_t g_pair[(size_t)N_NODES * 128];

typedef unsigned long long u64;

// ---- cache-policy loads (createpolicy + cache_hint) ---------------------------
__device__ __forceinline__ u64 make_evict_last_policy() {
    u64 pol;
    asm("createpolicy.fractional.L2::evict_last.b64 %0, 1.0;" : "=l"(pol));
    return pol;
}
__device__ __forceinline__ float4 ldg_keep(const float* p, u64 pol) {
    float4 v;
    asm("ld.global.nc.L2::cache_hint.v4.f32 {%0,%1,%2,%3}, [%4], %5;"
        : "=f"(v.x), "=f"(v.y), "=f"(v.z), "=f"(v.w) : "l"(p), "l"(pol));
    return v;
}
__device__ __forceinline__ uint4 ldg_keep4u(const uint32_t* p, u64 pol) {
    uint4 v;
    asm("ld.global.nc.L2::cache_hint.v4.b32 {%0,%1,%2,%3}, [%4], %5;"
        : "=r"(v.x), "=r"(v.y), "=r"(v.z), "=r"(v.w) : "l"(p), "l"(pol));
    return v;
}

// ---- tf32 helpers --------------------------------------------------------------
__device__ __forceinline__ uint32_t f2tf32(float x) {
    uint32_t r;
    asm("cvt.rna.tf32.f32 %0, %1;" : "=r"(r) : "f"(x));
    return r;
}
__device__ __forceinline__ void mma_tf32(float* d, const uint32_t* a, const uint32_t* b) {
    asm volatile(
        "mma.sync.aligned.m16n8k8.row.col.f32.tf32.tf32.f32 "
        "{%0,%1,%2,%3}, {%4,%5,%6,%7}, {%8,%9}, {%0,%1,%2,%3};"
        : "+f"(d[0]), "+f"(d[1]), "+f"(d[2]), "+f"(d[3])
        : "r"(a[0]), "r"(a[1]), "r"(a[2]), "r"(a[3]), "r"(b[0]), "r"(b[1]));
}

// ---------------------------------------------------------------------------
// Kernel 1: tf32 tensor-core GEMM  [100000 x 128] @ [128 x 128] (x2 halves).
// CTA: 256 thr = 8 warps (2m x 4n), BM=128, BN=128, K staged 16, dbl-buffered.
// Half 0 -> g_X1 fp32 (+b1).
// Half 1 -> bf16 X2 into g_pair slots; its A-loader also emits the fp16
//           latents copy into g_pair (data already in registers — free read).
// ---------------------------------------------------------------------------
#define GBK 16
#define APAD 20    // floats per A row (16 + 4)
#define BPAD 136   // floats per B row (128 + 8)

__global__ __launch_bounds__(256, 2) void mlp1_gemm_mma(const float* __restrict__ lat,
                                                        const float* __restrict__ W1,
                                                        const float* __restrict__ b1) {
    const int half = blockIdx.y;
    const float* __restrict__ Bsrc = W1 + (half ? (DIM * DIM) : 0); // [k][n] row-major
    const int m0 = blockIdx.x * 128;
    const u64 pol = make_evict_last_policy();

    __shared__ uint32_t Asm[2][128][APAD];
    __shared__ uint32_t Bsm[2][GBK][BPAD];
    __shared__ float    sb1[DIM];

    const int tid   = threadIdx.x;
    const int wid   = tid >> 5;
    const int lane  = tid & 31;
    const int warpm = (wid >> 2) * 64;   // 0 or 64
    const int warpn = (wid & 3) * 32;    // 0,32,64,96
    const int r     = lane >> 2;         // 0..7
    const int c     = lane & 3;          // 0..3

    if (tid < DIM) sb1[tid] = b1[tid];

    float acc[4][4][4];
#pragma unroll
    for (int tm = 0; tm < 4; tm++)
#pragma unroll
        for (int tn = 0; tn < 4; tn++)
#pragma unroll
            for (int q = 0; q < 4; q++) acc[tm][tn][q] = 0.f;

    // Stage loader: A[128m x 16k] + B[16k x 128n] at k-offset k0 into buf.
    // In half 1, the A data is also emitted as the fp16 latents copy in g_pair.
    auto load_stage = [&](int buf, int k0) {
#pragma unroll
        for (int i = 0; i < 2; i++) {           // A: 512 float4 / 256 thr
            int f   = i * 256 + tid;
            int row = f >> 2;                   // 0..127
            int cq  = (f & 3) * 4;              // 0,4,8,12
            int gm  = m0 + row;
            if (gm >= N_NODES) gm = N_NODES - 1;
            float4 v = ldg_keep(lat + (size_t)gm * DIM + k0 + cq, pol);
            if (half) {
                // fp16 latents into g_pair: dims d0..d0+3, d0 = k0+cq (mult of 4).
                const int d0 = k0 + cq;
                __half2 lo = __floats2half2_rn(v.x, v.y);
                __half2 hi = __floats2half2_rn(v.z, v.w);
                uint2 w;
                w.x = *(uint32_t*)&lo;
                w.y = *(uint32_t*)&hi;
                *(uint2*)(&g_pair[(size_t)gm * 128 + (size_t)(d0 >> 2) * 4 + 2]) = w;
            }
            uint4 t;
            t.x = f2tf32(v.x); t.y = f2tf32(v.y); t.z = f2tf32(v.z); t.w = f2tf32(v.w);
            *(uint4*)(&Asm[buf][row][cq]) = t;
        }
#pragma unroll
        for (int i = 0; i < 2; i++) {           // B: 512 float4 / 256 thr
            int f  = i * 256 + tid;
            int kr = f >> 5;                    // 0..15
            int cq = (f & 31) * 4;              // 0..124
            float4 v = *(const float4*)(Bsrc + (size_t)(k0 + kr) * DIM + cq);
            uint4 t;
            t.x = f2tf32(v.x); t.y = f2tf32(v.y); t.z = f2tf32(v.z); t.w = f2tf32(v.w);
            *(uint4*)(&Bsm[buf][kr][cq]) = t;
        }
    };

    load_stage(0, 0);
    __syncthreads();

    int s = 0;
    for (int k0 = 0; k0 < DIM; k0 += GBK, s ^= 1) {
        if (k0 + GBK < DIM) load_stage(s ^ 1, k0 + GBK);

#pragma unroll
        for (int ch = 0; ch < 2; ch++) {
            const int kc = ch * 8;
            uint32_t af[4][4];
#pragma unroll
            for (int tm = 0; tm < 4; tm++) {
                const int mr = warpm + tm * 16;
                af[tm][0] = Asm[s][mr + r    ][kc + c];
                af[tm][1] = Asm[s][mr + r + 8][kc + c];
                af[tm][2] = Asm[s][mr + r    ][kc + c + 4];
                af[tm][3] = Asm[s][mr + r + 8][kc + c + 4];
            }
            uint32_t bf[4][2];
#pragma unroll
            for (int tn = 0; tn < 4; tn++) {
                const int nc = warpn + tn * 8;
                bf[tn][0] = Bsm[s][kc + c    ][nc + r];
                bf[tn][1] = Bsm[s][kc + c + 4][nc + r];
            }
#pragma unroll
            for (int tm = 0; tm < 4; tm++)
#pragma unroll
                for (int tn = 0; tn < 4; tn++)
                    mma_tf32(acc[tm][tn], af[tm], bf[tn]);
        }
        __syncthreads();
    }

    // Epilogue. C frag: c0,c1 @ (row=r, col=2c,2c+1); c2,c3 @ (row=r+8).
    if (half == 0) {
#pragma unroll
        for (int tm = 0; tm < 4; tm++) {
            const int gmA = m0 + warpm + tm * 16 + r;
            const int gmB = gmA + 8;
#pragma unroll
            for (int tn = 0; tn < 4; tn++) {
                const int nc = warpn + tn * 8 + 2 * c;
                const float bx = sb1[nc], by = sb1[nc + 1];
                if (gmA < N_NODES) {
                    float2 v = make_float2(acc[tm][tn][0] + bx, acc[tm][tn][1] + by);
                    *(float2*)(g_X1 + (size_t)gmA * DIM + nc) = v;
                }
                if (gmB < N_NODES) {
                    float2 v = make_float2(acc[tm][tn][2] + bx, acc[tm][tn][3] + by);
                    *(float2*)(g_X1 + (size_t)gmB * DIM + nc) = v;
                }
            }
        }
    } else {
        // X2 -> bf16 slots of g_pair: dims (nc, nc+1) -> uint32 index
        // (nc>>2)*4 + ((nc&2)>>1) within the row.
#pragma unroll
        for (int tm = 0; tm < 4; tm++) {
            const int gmA = m0 + warpm + tm * 16 + r;
            const int gmB = gmA + 8;
#pragma unroll
            for (int tn = 0; tn < 4; tn++) {
                const int nc  = warpn + tn * 8 + 2 * c;
                const int idx = ((nc >> 2) << 2) + ((nc & 2) >> 1);
                if (gmA < N_NODES) {
                    __nv_bfloat162 h = __floats2bfloat162_rn(acc[tm][tn][0], acc[tm][tn][1]);
                    g_pair[(size_t)gmA * 128 + idx] = *(uint32_t*)&h;
                }
                if (gmB < N_NODES) {
                    __nv_bfloat162 h = __floats2bfloat162_rn(acc[tm][tn][2], acc[tm][tn][3]);
                    g_pair[(size_t)gmB * 128 + idx] = *(uint32_t*)&h;
                }
            }
        }
    }
}

// ---------------------------------------------------------------------------
// Kernel 2: fused gather / score / ONLINE-softmax / weighted sum.
// One warp per node. ONE LDG.128 per neighbor per lane from the fused g_pair
// row (bf16 X2 + fp16 lat together) — 512 B/row vs 768 B before.
// ---------------------------------------------------------------------------
__global__ __launch_bounds__(128) void attend_kernel(const int* __restrict__ nbr,
                                                     const float* __restrict__ W2,
                                                     float* __restrict__ out) {
    __shared__ float s_w2[DIM];
    const int tid = threadIdx.x;
    s_w2[tid] = W2[tid];
    __syncthreads();

    const int n = blockIdx.x * 4 + (tid >> 5);
    if (n >= N_NODES) return;
    const int lane = tid & 31;
    const u64 pol = make_evict_last_policy();

    const float4 x1  = __ldcs((const float4*)(g_X1 + (size_t)n * DIM + lane * 4));
    const float4 w2v = *(const float4*)(s_w2 + lane * 4);
    const uint32_t lane4 = (uint32_t)lane << 2;   // uint32 offset within row

    int js[KNB];
    {
        const int4* p = (const int4*)(nbr + (size_t)n * KNB);
#pragma unroll
        for (int q = 0; q < 4; q++) {
            int4 v = __ldcs(p + q);
            js[q * 4 + 0] = v.x;
            js[q * 4 + 1] = v.y;
            js[q * 4 + 2] = v.z;
            js[q * 4 + 3] = v.w;
        }
    }

    float  rm = -__int_as_float(0x7f800000);  // running max = -inf
    float  rz = 0.f;                          // running sum
    float4 acc = make_float4(0.f, 0.f, 0.f, 0.f);

#pragma unroll
    for (int g = 0; g < 4; g++) {
        uint4 q[4];
#pragma unroll
        for (int t = 0; t < 4; t++) {
            const uint32_t ro = ((uint32_t)js[g * 4 + t] << 7) + lane4;
            q[t] = ldg_keep4u(g_pair + ro, pol);
        }

        float p[4];
#pragma unroll
        for (int t = 0; t < 4; t++) {
            const float2 f0 = __bfloat1622float2(*(const __nv_bfloat162*)&q[t].x);
            const float2 f1 = __bfloat1622float2(*(const __nv_bfloat162*)&q[t].y);
            float s = fmaxf(x1.x + f0.x, 0.f) * w2v.x;
            s = fmaf(fmaxf(x1.y + f0.y, 0.f), w2v.y, s);
            s = fmaf(fmaxf(x1.z + f1.x, 0.f), w2v.z, s);
            s = fmaf(fmaxf(x1.w + f1.y, 0.f), w2v.w, s);
            p[t] = s;
        }
#pragma unroll
        for (int d = 16; d > 0; d >>= 1) {
            p[0] += __shfl_xor_sync(0xffffffffu, p[0], d);
            p[1] += __shfl_xor_sync(0xffffffffu, p[1], d);
            p[2] += __shfl_xor_sync(0xffffffffu, p[2], d);
            p[3] += __shfl_xor_sync(0xffffffffu, p[3], d);
        }
#pragma unroll
        for (int t = 0; t < 4; t++) {
            const float2 l0 = __half22float2(*(const __half2*)&q[t].z);
            const float2 l1 = __half22float2(*(const __half2*)&q[t].w);
            const float sv = p[t];
            const float mn = fmaxf(rm, sv);
            const float f  = __expf(rm - mn);   // exp(-inf)=0 on first item
            const float e  = __expf(sv - mn);
            rm = mn;
            rz = fmaf(rz, f, e);
            acc.x = fmaf(acc.x, f, e * l0.x);
            acc.y = fmaf(acc.y, f, e * l0.y);
            acc.z = fmaf(acc.z, f, e * l1.x);
            acc.w = fmaf(acc.w, f, e * l1.y);
        }
    }

    const float inv = 1.f / rz;
    float4 o;
    o.x = acc.x * inv;
    o.y = acc.y * inv;
    o.z = acc.z * inv;
    o.w = acc.w * inv;
    __stcs((float4*)(out + (size_t)n * DIM + lane * 4), o);
}

// ---------------------------------------------------------------------------
// Launch
// ---------------------------------------------------------------------------
extern "C" void kernel_launch(void* const* d_in, const int* in_sizes, int n_in,
                              void* d_out, int out_size) {
    const float* latents   = (const float*)d_in[0];
    const int*   neighbors = (const int*)d_in[1];   // int32 (JAX x64-disabled)
    const float* W1        = (const float*)d_in[2];
    const float* b1        = (const float*)d_in[3];
    const float* W2        = (const float*)d_in[4];
    // d_in[5] = b2: cancels in softmax.
    float* out = (float*)d_out;

    (void)in_sizes; (void)n_in; (void)out_size;

    dim3 ggrid((N_NODES + 127) / 128, 2);
    mlp1_gemm_mma<<<ggrid, 256>>>(latents, W1, b1);

    const int blocks = (N_NODES + 3) / 4;   // 4 warps (nodes) per 128-thread block
    attend_kernel<<<blocks, 128>>>(neighbors, W2, out);
}

// round 12
// speedup vs baseline: 2.4909x; 1.1294x over previous
#include <cuda_runtime.h>
#include <cuda_bf16.h>
#include <cuda_fp16.h>
#include <cstdint>

#define N_NODES 100000
#define DIM     128
#define KNB     16

// Scratch tables.
// g_X1: fp32, streamed once per node in attend.
__device__ float g_X1[(size_t)N_NODES * DIM];
// g_pair: fused gather table, 512 B per row j:
//   bytes [0,256):   128 x bf16  X2[j]   (dims in order)
//   bytes [256,512): 128 x fp16  lat[j]  (dims in order)
// A 16-lane half-warp reads a row with 2 x LDG.128 per lane (16B X2 + 16B lat).
__device__ uint32_t g_pair[(size_t)N_NODES * 128];

typedef unsigned long long u64;

// ---- cache-policy loads (createpolicy + cache_hint) ---------------------------
__device__ __forceinline__ u64 make_evict_last_policy() {
    u64 pol;
    asm("createpolicy.fractional.L2::evict_last.b64 %0, 1.0;" : "=l"(pol));
    return pol;
}
__device__ __forceinline__ float4 ldg_keep(const float* p, u64 pol) {
    float4 v;
    asm("ld.global.nc.L2::cache_hint.v4.f32 {%0,%1,%2,%3}, [%4], %5;"
        : "=f"(v.x), "=f"(v.y), "=f"(v.z), "=f"(v.w) : "l"(p), "l"(pol));
    return v;
}
__device__ __forceinline__ uint4 ldg_keep4u(const uint32_t* p, u64 pol) {
    uint4 v;
    asm("ld.global.nc.L2::cache_hint.v4.b32 {%0,%1,%2,%3}, [%4], %5;"
        : "=r"(v.x), "=r"(v.y), "=r"(v.z), "=r"(v.w) : "l"(p), "l"(pol));
    return v;
}

// ---- tf32 helpers --------------------------------------------------------------
__device__ __forceinline__ uint32_t f2tf32(float x) {
    uint32_t r;
    asm("cvt.rna.tf32.f32 %0, %1;" : "=r"(r) : "f"(x));
    return r;
}
__device__ __forceinline__ void mma_tf32(float* d, const uint32_t* a, const uint32_t* b) {
    asm volatile(
        "mma.sync.aligned.m16n8k8.row.col.f32.tf32.tf32.f32 "
        "{%0,%1,%2,%3}, {%4,%5,%6,%7}, {%8,%9}, {%0,%1,%2,%3};"
        : "+f"(d[0]), "+f"(d[1]), "+f"(d[2]), "+f"(d[3])
        : "r"(a[0]), "r"(a[1]), "r"(a[2]), "r"(a[3]), "r"(b[0]), "r"(b[1]));
}

// ---------------------------------------------------------------------------
// Kernel 1: tf32 tensor-core GEMM  [100000 x 128] @ [128 x 128] (x2 halves).
// CTA: 256 thr = 8 warps (2m x 4n), BM=128, BN=128, K staged 16, dbl-buffered.
// Half 0 -> g_X1 fp32 (+b1).
// Half 1 -> bf16 X2 into g_pair[0,256) slots; its A-loader also emits the
//           fp16 latents copy into g_pair[256,512) (data already in regs).
// ---------------------------------------------------------------------------
#define GBK 16
#define APAD 20    // u32 per A row (16 + 4)
#define BPAD 136   // u32 per B row (128 + 8)

__global__ __launch_bounds__(256, 2) void mlp1_gemm_mma(const float* __restrict__ lat,
                                                        const float* __restrict__ W1,
                                                        const float* __restrict__ b1) {
    const int half = blockIdx.y;
    const float* __restrict__ Bsrc = W1 + (half ? (DIM * DIM) : 0); // [k][n] row-major
    const int m0 = blockIdx.x * 128;
    const u64 pol = make_evict_last_policy();

    __shared__ uint32_t Asm[2][128][APAD];
    __shared__ uint32_t Bsm[2][GBK][BPAD];
    __shared__ float    sb1[DIM];

    const int tid   = threadIdx.x;
    const int wid   = tid >> 5;
    const int lane  = tid & 31;
    const int warpm = (wid >> 2) * 64;   // 0 or 64
    const int warpn = (wid & 3) * 32;    // 0,32,64,96
    const int r     = lane >> 2;         // 0..7
    const int c     = lane & 3;          // 0..3

    if (tid < DIM) sb1[tid] = b1[tid];

    float acc[4][4][4];
#pragma unroll
    for (int tm = 0; tm < 4; tm++)
#pragma unroll
        for (int tn = 0; tn < 4; tn++)
#pragma unroll
            for (int q = 0; q < 4; q++) acc[tm][tn][q] = 0.f;

    // Stage loader: A[128m x 16k] + B[16k x 128n] at k-offset k0 into buf.
    auto load_stage = [&](int buf, int k0) {
#pragma unroll
        for (int i = 0; i < 2; i++) {           // A: 512 float4 / 256 thr
            int f   = i * 256 + tid;
            int row = f >> 2;                   // 0..127
            int cq  = (f & 3) * 4;              // 0,4,8,12
            int gm  = m0 + row;
            if (gm >= N_NODES) gm = N_NODES - 1;
            float4 v = ldg_keep(lat + (size_t)gm * DIM + k0 + cq, pol);
            if (half) {
                // fp16 latents into g_pair block [256,512): dims d0..d0+3.
                const int d0 = k0 + cq;
                __half2 lo = __floats2half2_rn(v.x, v.y);
                __half2 hi = __floats2half2_rn(v.z, v.w);
                uint2 w;
                w.x = *(uint32_t*)&lo;
                w.y = *(uint32_t*)&hi;
                *(uint2*)(&g_pair[(size_t)gm * 128 + 64 + (d0 >> 1)]) = w;
            }
            uint4 t;
            t.x = f2tf32(v.x); t.y = f2tf32(v.y); t.z = f2tf32(v.z); t.w = f2tf32(v.w);
            *(uint4*)(&Asm[buf][row][cq]) = t;
        }
#pragma unroll
        for (int i = 0; i < 2; i++) {           // B: 512 float4 / 256 thr
            int f  = i * 256 + tid;
            int kr = f >> 5;                    // 0..15
            int cq = (f & 31) * 4;              // 0..124
            float4 v = *(const float4*)(Bsrc + (size_t)(k0 + kr) * DIM + cq);
            uint4 t;
            t.x = f2tf32(v.x); t.y = f2tf32(v.y); t.z = f2tf32(v.z); t.w = f2tf32(v.w);
            *(uint4*)(&Bsm[buf][kr][cq]) = t;
        }
    };

    load_stage(0, 0);
    __syncthreads();

    int s = 0;
    for (int k0 = 0; k0 < DIM; k0 += GBK, s ^= 1) {
        if (k0 + GBK < DIM) load_stage(s ^ 1, k0 + GBK);

#pragma unroll
        for (int ch = 0; ch < 2; ch++) {
            const int kc = ch * 8;
            uint32_t af[4][4];
#pragma unroll
            for (int tm = 0; tm < 4; tm++) {
                const int mr = warpm + tm * 16;
                af[tm][0] = Asm[s][mr + r    ][kc + c];
                af[tm][1] = Asm[s][mr + r + 8][kc + c];
                af[tm][2] = Asm[s][mr + r    ][kc + c + 4];
                af[tm][3] = Asm[s][mr + r + 8][kc + c + 4];
            }
            uint32_t bf[4][2];
#pragma unroll
            for (int tn = 0; tn < 4; tn++) {
                const int nc = warpn + tn * 8;
                bf[tn][0] = Bsm[s][kc + c    ][nc + r];
                bf[tn][1] = Bsm[s][kc + c + 4][nc + r];
            }
#pragma unroll
            for (int tm = 0; tm < 4; tm++)
#pragma unroll
                for (int tn = 0; tn < 4; tn++)
                    mma_tf32(acc[tm][tn], af[tm], bf[tn]);
        }
        __syncthreads();
    }

    // Epilogue. C frag: c0,c1 @ (row=r, col=2c,2c+1); c2,c3 @ (row=r+8).
    if (half == 0) {
#pragma unroll
        for (int tm = 0; tm < 4; tm++) {
            const int gmA = m0 + warpm + tm * 16 + r;
            const int gmB = gmA + 8;
#pragma unroll
            for (int tn = 0; tn < 4; tn++) {
                const int nc = warpn + tn * 8 + 2 * c;
                const float bx = sb1[nc], by = sb1[nc + 1];
                if (gmA < N_NODES) {
                    float2 v = make_float2(acc[tm][tn][0] + bx, acc[tm][tn][1] + by);
                    *(float2*)(g_X1 + (size_t)gmA * DIM + nc) = v;
                }
                if (gmB < N_NODES) {
                    float2 v = make_float2(acc[tm][tn][2] + bx, acc[tm][tn][3] + by);
                    *(float2*)(g_X1 + (size_t)gmB * DIM + nc) = v;
                }
            }
        }
    } else {
        // X2 -> bf16 block [0,256) of g_pair: dims (nc, nc+1) -> u32 idx nc>>1.
#pragma unroll
        for (int tm = 0; tm < 4; tm++) {
            const int gmA = m0 + warpm + tm * 16 + r;
            const int gmB = gmA + 8;
#pragma unroll
            for (int tn = 0; tn < 4; tn++) {
                const int nc = warpn + tn * 8 + 2 * c;
                if (gmA < N_NODES) {
                    __nv_bfloat162 h = __floats2bfloat162_rn(acc[tm][tn][0], acc[tm][tn][1]);
                    g_pair[(size_t)gmA * 128 + (nc >> 1)] = *(uint32_t*)&h;
                }
                if (gmB < N_NODES) {
                    __nv_bfloat162 h = __floats2bfloat162_rn(acc[tm][tn][2], acc[tm][tn][3]);
                    g_pair[(size_t)gmB * 128 + (nc >> 1)] = *(uint32_t*)&h;
                }
            }
        }
    }
}

// ---------------------------------------------------------------------------
// Kernel 2: fused gather / score / ONLINE-softmax / weighted sum.
// HALF-WARP per node: 16 lanes, lane owns 8 dims. Two nodes share every warp
// instruction for the scalar softmax chain, exps, and a 4-level shfl reduce.
// 100000 nodes / 8 per block = 12500 blocks exactly (no partial warps).
// ---------------------------------------------------------------------------
__global__ __launch_bounds__(128) void attend_kernel(const int* __restrict__ nbr,
                                                     const float* __restrict__ W2,
                                                     float* __restrict__ out) {
    __shared__ float s_w2[DIM];
    const int tid = threadIdx.x;
    s_w2[tid] = W2[tid];
    __syncthreads();

    const int n = blockIdx.x * 8 + (tid >> 4);   // node per half-warp
    const int sl = tid & 15;                     // sub-lane 0..15: dims sl*8..sl*8+7
    const u64 pol = make_evict_last_policy();

    const float4 x1a = __ldcs((const float4*)(g_X1 + (size_t)n * DIM + sl * 8));
    const float4 x1b = __ldcs((const float4*)(g_X1 + (size_t)n * DIM + sl * 8 + 4));
    const float4 w2a = *(const float4*)(s_w2 + sl * 8);
    const float4 w2b = *(const float4*)(s_w2 + sl * 8 + 4);

    const uint32_t sl4 = (uint32_t)sl << 2;      // u32 offset of this lane's slice

    float rm = -__int_as_float(0x7f800000);      // running max = -inf
    float rz = 0.f;
    float acc[8];
#pragma unroll
    for (int i = 0; i < 8; i++) acc[i] = 0.f;

#pragma unroll
    for (int g = 0; g < 4; g++) {
        const int4 jv = __ldcs((const int4*)(nbr + (size_t)n * KNB + g * 4));
        const int js4[4] = {jv.x, jv.y, jv.z, jv.w};

        uint4 xq[4], lq[4];
#pragma unroll
        for (int t = 0; t < 4; t++) {
            const uint32_t ro = ((uint32_t)js4[t] << 7) + sl4;   // row base (u32 units)
            xq[t] = ldg_keep4u(g_pair + ro, pol);                // 8 bf16 X2 dims
            lq[t] = ldg_keep4u(g_pair + ro + 64, pol);           // 8 fp16 lat dims
        }

        float p[4];
#pragma unroll
        for (int t = 0; t < 4; t++) {
            const float2 a0 = __bfloat1622float2(*(const __nv_bfloat162*)&xq[t].x);
            const float2 a1 = __bfloat1622float2(*(const __nv_bfloat162*)&xq[t].y);
            const float2 a2 = __bfloat1622float2(*(const __nv_bfloat162*)&xq[t].z);
            const float2 a3 = __bfloat1622float2(*(const __nv_bfloat162*)&xq[t].w);
            float s = fmaxf(x1a.x + a0.x, 0.f) * w2a.x;
            s = fmaf(fmaxf(x1a.y + a0.y, 0.f), w2a.y, s);
            s = fmaf(fmaxf(x1a.z + a1.x, 0.f), w2a.z, s);
            s = fmaf(fmaxf(x1a.w + a1.y, 0.f), w2a.w, s);
            s = fmaf(fmaxf(x1b.x + a2.x, 0.f), w2b.x, s);
            s = fmaf(fmaxf(x1b.y + a2.y, 0.f), w2b.y, s);
            s = fmaf(fmaxf(x1b.z + a3.x, 0.f), w2b.z, s);
            s = fmaf(fmaxf(x1b.w + a3.y, 0.f), w2b.w, s);
            p[t] = s;
        }
        // 4-level reduce within the 16-lane half (xor 8,4,2,1 never crosses).
#pragma unroll
        for (int d = 8; d > 0; d >>= 1) {
            p[0] += __shfl_xor_sync(0xffffffffu, p[0], d);
            p[1] += __shfl_xor_sync(0xffffffffu, p[1], d);
            p[2] += __shfl_xor_sync(0xffffffffu, p[2], d);
            p[3] += __shfl_xor_sync(0xffffffffu, p[3], d);
        }
        // Online-softmax update; lat halves still live in lq.
#pragma unroll
        for (int t = 0; t < 4; t++) {
            const float2 l0 = __half22float2(*(const __half2*)&lq[t].x);
            const float2 l1 = __half22float2(*(const __half2*)&lq[t].y);
            const float2 l2 = __half22float2(*(const __half2*)&lq[t].z);
            const float2 l3 = __half22float2(*(const __half2*)&lq[t].w);
            const float sv = p[t];
            const float mn = fmaxf(rm, sv);
            const float f  = __expf(rm - mn);   // exp(-inf)=0 on first item
            const float e  = __expf(sv - mn);
            rm = mn;
            rz = fmaf(rz, f, e);
            acc[0] = fmaf(acc[0], f, e * l0.x);
            acc[1] = fmaf(acc[1], f, e * l0.y);
            acc[2] = fmaf(acc[2], f, e * l1.x);
            acc[3] = fmaf(acc[3], f, e * l1.y);
            acc[4] = fmaf(acc[4], f, e * l2.x);
            acc[5] = fmaf(acc[5], f, e * l2.y);
            acc[6] = fmaf(acc[6], f, e * l3.x);
            acc[7] = fmaf(acc[7], f, e * l3.y);
        }
    }

    const float inv = 1.f / rz;
    float4 o0, o1;
    o0.x = acc[0] * inv; o0.y = acc[1] * inv; o0.z = acc[2] * inv; o0.w = acc[3] * inv;
    o1.x = acc[4] * inv; o1.y = acc[5] * inv; o1.z = acc[6] * inv; o1.w = acc[7] * inv;
    __stcs((float4*)(out + (size_t)n * DIM + sl * 8), o0);
    __stcs((float4*)(out + (size_t)n * DIM + sl * 8 + 4), o1);
}

// ---------------------------------------------------------------------------
// Launch
// ---------------------------------------------------------------------------
extern "C" void kernel_launch(void* const* d_in, const int* in_sizes, int n_in,
                              void* d_out, int out_size) {
    const float* latents   = (const float*)d_in[0];
    const int*   neighbors = (const int*)d_in[1];   // int32 (JAX x64-disabled)
    const float* W1        = (const float*)d_in[2];
    const float* b1        = (const float*)d_in[3];
    const float* W2        = (const float*)d_in[4];
    // d_in[5] = b2: cancels in softmax.
    float* out = (float*)d_out;

    (void)in_sizes; (void)n_in; (void)out_size;

    dim3 ggrid((N_NODES + 127) / 128, 2);
    mlp1_gemm_mma<<<ggrid, 256>>>(latents, W1, b1);

    const int blocks = N_NODES / 8;   // 12500, exact: 8 nodes (half-warps) per block
    attend_kernel<<<blocks, 128>>>(neighbors, W2, out);
}

// round 13
// speedup vs baseline: 2.5901x; 1.0398x over previous
#include <cuda_runtime.h>
#include <cuda_bf16.h>
#include <cuda_fp16.h>
#include <cstdint>

#define N_NODES 100000
#define DIM     128
#define KNB     16

// Scratch tables.
__device__ float g_X1[(size_t)N_NODES * DIM];
// g_pair: fused gather table, 512 B per row j:
//   bytes [0,256):   128 x bf16  X2[j]
//   bytes [256,512): 128 x fp16  lat[j]
__device__ uint32_t g_pair[(size_t)N_NODES * 128];

typedef unsigned long long u64;

// ---- cache-policy loads ------------------------------------------------------
__device__ __forceinline__ u64 make_evict_last_policy() {
    u64 pol;
    asm("createpolicy.fractional.L2::evict_last.b64 %0, 1.0;" : "=l"(pol));
    return pol;
}
__device__ __forceinline__ float4 ldg_keep(const float* p, u64 pol) {
    float4 v;
    asm("ld.global.nc.L2::cache_hint.v4.f32 {%0,%1,%2,%3}, [%4], %5;"
        : "=f"(v.x), "=f"(v.y), "=f"(v.z), "=f"(v.w) : "l"(p), "l"(pol));
    return v;
}
__device__ __forceinline__ uint4 ldg_keep4u(const uint32_t* p, u64 pol) {
    uint4 v;
    asm("ld.global.nc.L2::cache_hint.v4.b32 {%0,%1,%2,%3}, [%4], %5;"
        : "=r"(v.x), "=r"(v.y), "=r"(v.z), "=r"(v.w) : "l"(p), "l"(pol));
    return v;
}

// ---- tf32 helpers --------------------------------------------------------------
__device__ __forceinline__ uint32_t f2tf32(float x) {
    uint32_t r;
    asm("cvt.rna.tf32.f32 %0, %1;" : "=r"(r) : "f"(x));
    return r;
}
__device__ __forceinline__ void mma_tf32(float* d, const uint32_t* a, const uint32_t* b) {
    asm volatile(
        "mma.sync.aligned.m16n8k8.row.col.f32.tf32.tf32.f32 "
        "{%0,%1,%2,%3}, {%4,%5,%6,%7}, {%8,%9}, {%0,%1,%2,%3};"
        : "+f"(d[0]), "+f"(d[1]), "+f"(d[2]), "+f"(d[3])
        : "r"(a[0]), "r"(a[1]), "r"(a[2]), "r"(a[3]), "r"(b[0]), "r"(b[1]));
}

// ---------------------------------------------------------------------------
// Kernel 1: tf32 tensor-core GEMM with REGISTER-STAGED prefetch.
// Stage s: [prefetch LDGs for s+1] -> mainloop(s) -> [cvt+STS s+1] -> sync.
// Half 0 -> g_X1 fp32 (+b1). Half 1 -> bf16 X2 + fp16 lat copy into g_pair.
// ---------------------------------------------------------------------------
#define GBK 16
#define APAD 20    // u32 per A row (16 + 4)
#define BPAD 136   // u32 per B row (128 + 8)

__global__ __launch_bounds__(256, 2) void mlp1_gemm_mma(const float* __restrict__ lat,
                                                        const float* __restrict__ W1,
                                                        const float* __restrict__ b1) {
    const int half = blockIdx.y;
    const float* __restrict__ Bsrc = W1 + (half ? (DIM * DIM) : 0); // [k][n] row-major
    const int m0 = blockIdx.x * 128;
    const u64 pol = make_evict_last_policy();

    __shared__ uint32_t Asm[2][128][APAD];
    __shared__ uint32_t Bsm[2][GBK][BPAD];
    __shared__ float    sb1[DIM];

    const int tid   = threadIdx.x;
    const int wid   = tid >> 5;
    const int lane  = tid & 31;
    const int warpm = (wid >> 2) * 64;   // 0 or 64
    const int warpn = (wid & 3) * 32;    // 0,32,64,96
    const int r     = lane >> 2;         // 0..7
    const int c     = lane & 3;          // 0..3

    if (tid < DIM) sb1[tid] = b1[tid];

    // Fixed per-thread load coordinates.
    const int a_row = tid >> 2;              // 0..63
    const int a_cq  = (tid & 3) * 4;         // 0,4,8,12
    int a_gm0 = m0 + a_row;       if (a_gm0 >= N_NODES) a_gm0 = N_NODES - 1;
    int a_gm1 = m0 + a_row + 64;  if (a_gm1 >= N_NODES) a_gm1 = N_NODES - 1;
    const int b_kr = tid >> 5;               // 0..7
    const int b_cq = (tid & 31) * 4;         // 0..124

    float acc[4][4][4];
#pragma unroll
    for (int tm = 0; tm < 4; tm++)
#pragma unroll
        for (int tn = 0; tn < 4; tn++)
#pragma unroll
            for (int q = 0; q < 4; q++) acc[tm][tn][q] = 0.f;

    float4 va0, va1, vb0, vb1;                 // prefetch registers

    auto prefetch = [&](int k0) {
        va0 = ldg_keep(lat + (size_t)a_gm0 * DIM + k0 + a_cq, pol);
        va1 = ldg_keep(lat + (size_t)a_gm1 * DIM + k0 + a_cq, pol);
        vb0 = *(const float4*)(Bsrc + (size_t)(k0 + b_kr) * DIM + b_cq);
        vb1 = *(const float4*)(Bsrc + (size_t)(k0 + 8 + b_kr) * DIM + b_cq);
    };
    auto commit = [&](int buf, int k0) {
        if (half) {
            // fp16 latents copy into g_pair [256,512): dims k0+a_cq .. +3.
            const int d0 = k0 + a_cq;
            __half2 lo, hi; uint2 w;
            lo = __floats2half2_rn(va0.x, va0.y); hi = __floats2half2_rn(va0.z, va0.w);
            w.x = *(uint32_t*)&lo; w.y = *(uint32_t*)&hi;
            *(uint2*)(&g_pair[(size_t)a_gm0 * 128 + 64 + (d0 >> 1)]) = w;
            lo = __floats2half2_rn(va1.x, va1.y); hi = __floats2half2_rn(va1.z, va1.w);
            w.x = *(uint32_t*)&lo; w.y = *(uint32_t*)&hi;
            *(uint2*)(&g_pair[(size_t)a_gm1 * 128 + 64 + (d0 >> 1)]) = w;
        }
        uint4 t;
        t.x = f2tf32(va0.x); t.y = f2tf32(va0.y); t.z = f2tf32(va0.z); t.w = f2tf32(va0.w);
        *(uint4*)(&Asm[buf][a_row][a_cq]) = t;
        t.x = f2tf32(va1.x); t.y = f2tf32(va1.y); t.z = f2tf32(va1.z); t.w = f2tf32(va1.w);
        *(uint4*)(&Asm[buf][a_row + 64][a_cq]) = t;
        t.x = f2tf32(vb0.x); t.y = f2tf32(vb0.y); t.z = f2tf32(vb0.z); t.w = f2tf32(vb0.w);
        *(uint4*)(&Bsm[buf][b_kr][b_cq]) = t;
        t.x = f2tf32(vb1.x); t.y = f2tf32(vb1.y); t.z = f2tf32(vb1.z); t.w = f2tf32(vb1.w);
        *(uint4*)(&Bsm[buf][b_kr + 8][b_cq]) = t;
    };

    prefetch(0);
    commit(0, 0);
    __syncthreads();

    int s = 0;
    for (int k0 = 0; k0 < DIM; k0 += GBK, s ^= 1) {
        const bool more = (k0 + GBK) < DIM;
        if (more) prefetch(k0 + GBK);        // LDG latency hides under mainloop

#pragma unroll
        for (int ch = 0; ch < 2; ch++) {
            const int kc = ch * 8;
            uint32_t af[4][4];
#pragma unroll
            for (int tm = 0; tm < 4; tm++) {
                const int mr = warpm + tm * 16;
                af[tm][0] = Asm[s][mr + r    ][kc + c];
                af[tm][1] = Asm[s][mr + r + 8][kc + c];
                af[tm][2] = Asm[s][mr + r    ][kc + c + 4];
                af[tm][3] = Asm[s][mr + r + 8][kc + c + 4];
            }
            uint32_t bf[4][2];
#pragma unroll
            for (int tn = 0; tn < 4; tn++) {
                const int nc = warpn + tn * 8;
                bf[tn][0] = Bsm[s][kc + c    ][nc + r];
                bf[tn][1] = Bsm[s][kc + c + 4][nc + r];
            }
#pragma unroll
            for (int tm = 0; tm < 4; tm++)
#pragma unroll
                for (int tn = 0; tn < 4; tn++)
                    mma_tf32(acc[tm][tn], af[tm], bf[tn]);
        }

        if (more) commit(s ^ 1, k0 + GBK);
        __syncthreads();
    }

    // Epilogue. C frag: c0,c1 @ (row=r, col=2c,2c+1); c2,c3 @ (row=r+8).
    if (half == 0) {
#pragma unroll
        for (int tm = 0; tm < 4; tm++) {
            const int gmA = m0 + warpm + tm * 16 + r;
            const int gmB = gmA + 8;
#pragma unroll
            for (int tn = 0; tn < 4; tn++) {
                const int nc = warpn + tn * 8 + 2 * c;
                const float bx = sb1[nc], by = sb1[nc + 1];
                if (gmA < N_NODES) {
                    float2 v = make_float2(acc[tm][tn][0] + bx, acc[tm][tn][1] + by);
                    *(float2*)(g_X1 + (size_t)gmA * DIM + nc) = v;
                }
                if (gmB < N_NODES) {
                    float2 v = make_float2(acc[tm][tn][2] + bx, acc[tm][tn][3] + by);
                    *(float2*)(g_X1 + (size_t)gmB * DIM + nc) = v;
                }
            }
        }
    } else {
#pragma unroll
        for (int tm = 0; tm < 4; tm++) {
            const int gmA = m0 + warpm + tm * 16 + r;
            const int gmB = gmA + 8;
#pragma unroll
            for (int tn = 0; tn < 4; tn++) {
                const int nc = warpn + tn * 8 + 2 * c;
                if (gmA < N_NODES) {
                    __nv_bfloat162 h = __floats2bfloat162_rn(acc[tm][tn][0], acc[tm][tn][1]);
                    g_pair[(size_t)gmA * 128 + (nc >> 1)] = *(uint32_t*)&h;
                }
                if (gmB < N_NODES) {
                    __nv_bfloat162 h = __floats2bfloat162_rn(acc[tm][tn][2], acc[tm][tn][3]);
                    g_pair[(size_t)gmB * 128 + (nc >> 1)] = *(uint32_t*)&h;
                }
            }
        }
    }
}

// ---------------------------------------------------------------------------
// Kernel 2: HALF-WARP per node, TWO-PHASE softmax in registers.
// Phase A: gather bf16 X2 halves, compute sc[16] (W2 pre-scaled by log2e).
// Then: max-tree + 16x exp2f + sum (bare EX2, no online rescaling).
// Phase B: gather fp16 lat halves, weighted accumulate.
// ---------------------------------------------------------------------------
__global__ __launch_bounds__(128) void attend_kernel(const int* __restrict__ nbr,
                                                     const float* __restrict__ W2,
                                                     float* __restrict__ out) {
    __shared__ float s_w2[DIM];
    const int tid = threadIdx.x;
    s_w2[tid] = W2[tid] * 1.4426950408889634f;   // fold log2e: exp(s) = exp2(s')
    __syncthreads();

    const int n = blockIdx.x * 8 + (tid >> 4);   // node per half-warp (exact: 100000/8)
    const int sl = tid & 15;                     // sub-lane: dims sl*8..sl*8+7
    const u64 pol = make_evict_last_policy();

    const float4 x1a = __ldcs((const float4*)(g_X1 + (size_t)n * DIM + sl * 8));
    const float4 x1b = __ldcs((const float4*)(g_X1 + (size_t)n * DIM + sl * 8 + 4));
    const float4 w2a = *(const float4*)(s_w2 + sl * 8);
    const float4 w2b = *(const float4*)(s_w2 + sl * 8 + 4);

    const uint32_t sl4 = (uint32_t)sl << 2;

    // Row offsets for all 16 neighbors (u32 units into g_pair).
    uint32_t ro[KNB];
    {
#pragma unroll
        for (int q = 0; q < 4; q++) {
            const int4 jv = __ldcs((const int4*)(nbr + (size_t)n * KNB + q * 4));
            ro[q * 4 + 0] = ((uint32_t)jv.x << 7) + sl4;
            ro[q * 4 + 1] = ((uint32_t)jv.y << 7) + sl4;
            ro[q * 4 + 2] = ((uint32_t)jv.z << 7) + sl4;
            ro[q * 4 + 3] = ((uint32_t)jv.w << 7) + sl4;
        }
    }

    // Phase A: scores.
    float sc[KNB];
#pragma unroll
    for (int g = 0; g < 4; g++) {
        uint4 xq[4];
#pragma unroll
        for (int t = 0; t < 4; t++) xq[t] = ldg_keep4u(g_pair + ro[g * 4 + t], pol);

        float p[4];
#pragma unroll
        for (int t = 0; t < 4; t++) {
            const float2 a0 = __bfloat1622float2(*(const __nv_bfloat162*)&xq[t].x);
            const float2 a1 = __bfloat1622float2(*(const __nv_bfloat162*)&xq[t].y);
            const float2 a2 = __bfloat1622float2(*(const __nv_bfloat162*)&xq[t].z);
            const float2 a3 = __bfloat1622float2(*(const __nv_bfloat162*)&xq[t].w);
            float s = fmaxf(x1a.x + a0.x, 0.f) * w2a.x;
            s = fmaf(fmaxf(x1a.y + a0.y, 0.f), w2a.y, s);
            s = fmaf(fmaxf(x1a.z + a1.x, 0.f), w2a.z, s);
            s = fmaf(fmaxf(x1a.w + a1.y, 0.f), w2a.w, s);
            s = fmaf(fmaxf(x1b.x + a2.x, 0.f), w2b.x, s);
            s = fmaf(fmaxf(x1b.y + a2.y, 0.f), w2b.y, s);
            s = fmaf(fmaxf(x1b.z + a3.x, 0.f), w2b.z, s);
            s = fmaf(fmaxf(x1b.w + a3.y, 0.f), w2b.w, s);
            p[t] = s;
        }
#pragma unroll
        for (int d = 8; d > 0; d >>= 1) {
            p[0] += __shfl_xor_sync(0xffffffffu, p[0], d);
            p[1] += __shfl_xor_sync(0xffffffffu, p[1], d);
            p[2] += __shfl_xor_sync(0xffffffffu, p[2], d);
            p[3] += __shfl_xor_sync(0xffffffffu, p[3], d);
        }
        sc[g * 4 + 0] = p[0];
        sc[g * 4 + 1] = p[1];
        sc[g * 4 + 2] = p[2];
        sc[g * 4 + 3] = p[3];
    }

    // Softmax weights in registers (max-tree for ILP, bare EX2).
    float t8[8];
#pragma unroll
    for (int i = 0; i < 8; i++) t8[i] = fmaxf(sc[i], sc[i + 8]);
    float t4a = fmaxf(t8[0], t8[4]), t4b = fmaxf(t8[1], t8[5]);
    float t4c = fmaxf(t8[2], t8[6]), t4d = fmaxf(t8[3], t8[7]);
    const float m = fmaxf(fmaxf(t4a, t4b), fmaxf(t4c, t4d));

    float rz = 0.f;
#pragma unroll
    for (int k = 0; k < KNB; k++) {
        sc[k] = exp2f(sc[k] - m);
        rz += sc[k];
    }
    const float inv = 1.f / rz;
#pragma unroll
    for (int k = 0; k < KNB; k++) sc[k] *= inv;

    // Phase B: weighted accumulate over fp16 lat halves.
    float acc[8];
#pragma unroll
    for (int i = 0; i < 8; i++) acc[i] = 0.f;

#pragma unroll
    for (int g = 0; g < 4; g++) {
        uint4 lq[4];
#pragma unroll
        for (int t = 0; t < 4; t++) lq[t] = ldg_keep4u(g_pair + ro[g * 4 + t] + 64, pol);
#pragma unroll
        for (int t = 0; t < 4; t++) {
            const float2 l0 = __half22float2(*(const __half2*)&lq[t].x);
            const float2 l1 = __half22float2(*(const __half2*)&lq[t].y);
            const float2 l2 = __half22float2(*(const __half2*)&lq[t].z);
            const float2 l3 = __half22float2(*(const __half2*)&lq[t].w);
            const float w = sc[g * 4 + t];
            acc[0] = fmaf(w, l0.x, acc[0]);
            acc[1] = fmaf(w, l0.y, acc[1]);
            acc[2] = fmaf(w, l1.x, acc[2]);
            acc[3] = fmaf(w, l1.y, acc[3]);
            acc[4] = fmaf(w, l2.x, acc[4]);
            acc[5] = fmaf(w, l2.y, acc[5]);
            acc[6] = fmaf(w, l3.x, acc[6]);
            acc[7] = fmaf(w, l3.y, acc[7]);
        }
    }

    float4 o0, o1;
    o0.x = acc[0]; o0.y = acc[1]; o0.z = acc[2]; o0.w = acc[3];
    o1.x = acc[4]; o1.y = acc[5]; o1.z = acc[6]; o1.w = acc[7];
    __stcs((float4*)(out + (size_t)n * DIM + sl * 8), o0);
    __stcs((float4*)(out + (size_t)n * DIM + sl * 8 + 4), o1);
}

// ---------------------------------------------------------------------------
// Launch
// ---------------------------------------------------------------------------
extern "C" void kernel_launch(void* const* d_in, const int* in_sizes, int n_in,
                              void* d_out, int out_size) {
    const float* latents   = (const float*)d_in[0];
    const int*   neighbors = (const int*)d_in[1];   // int32 (JAX x64-disabled)
    const float* W1        = (const float*)d_in[2];
    const float* b1        = (const float*)d_in[3];
    const float* W2        = (const float*)d_in[4];
    // d_in[5] = b2: cancels in softmax.
    float* out = (float*)d_out;

    (void)in_sizes; (void)n_in; (void)out_size;

    dim3 ggrid((N_NODES + 127) / 128, 2);
    mlp1_gemm_mma<<<ggrid, 256>>>(latents, W1, b1);

    const int blocks = N_NODES / 8;   // 12500, exact: 8 nodes (half-warps) per block
    attend_kernel<<<blocks, 128>>>(neighbors, W2, out);
}

// round 14
// speedup vs baseline: 2.7323x; 1.0549x over previous
#include <cuda_runtime.h>
#include <cuda_bf16.h>
#include <cuda_fp16.h>
#include <cstdint>

#define N_NODES 100000
#define DIM     128
#define KNB     16

// Scratch tables.
__device__ float g_X1[(size_t)N_NODES * DIM];
// g_pair: fused gather table, 512 B per row j:
//   bytes [0,256):   128 x bf16  X2[j]
//   bytes [256,512): 128 x fp16  lat[j]
__device__ uint32_t g_pair[(size_t)N_NODES * 128];

typedef unsigned long long u64;

// ---- cache-policy loads ------------------------------------------------------
__device__ __forceinline__ u64 make_evict_last_policy() {
    u64 pol;
    asm("createpolicy.fractional.L2::evict_last.b64 %0, 1.0;" : "=l"(pol));
    return pol;
}
__device__ __forceinline__ float4 ldg_keep(const float* p, u64 pol) {
    float4 v;
    asm("ld.global.nc.L2::cache_hint.v4.f32 {%0,%1,%2,%3}, [%4], %5;"
        : "=f"(v.x), "=f"(v.y), "=f"(v.z), "=f"(v.w) : "l"(p), "l"(pol));
    return v;
}
__device__ __forceinline__ uint4 ldg_keep4u(const uint32_t* p, u64 pol) {
    uint4 v;
    asm("ld.global.nc.L2::cache_hint.v4.b32 {%0,%1,%2,%3}, [%4], %5;"
        : "=r"(v.x), "=r"(v.y), "=r"(v.z), "=r"(v.w) : "l"(p), "l"(pol));
    return v;
}

// ---- tf32 helpers --------------------------------------------------------------
__device__ __forceinline__ uint32_t f2tf32(float x) {
    uint32_t r;
    asm("cvt.rna.tf32.f32 %0, %1;" : "=r"(r) : "f"(x));
    return r;
}
__device__ __forceinline__ void mma_tf32(float* d, const uint32_t* a, const uint32_t* b) {
    asm volatile(
        "mma.sync.aligned.m16n8k8.row.col.f32.tf32.tf32.f32 "
        "{%0,%1,%2,%3}, {%4,%5,%6,%7}, {%8,%9}, {%0,%1,%2,%3};"
        : "+f"(d[0]), "+f"(d[1]), "+f"(d[2]), "+f"(d[3])
        : "r"(a[0]), "r"(a[1]), "r"(a[2]), "r"(a[3]), "r"(b[0]), "r"(b[1]));
}

// ---------------------------------------------------------------------------
// Kernel 1: tf32 tensor-core GEMM with register-staged prefetch.
// grid = (2 halves, 782 m-tiles): the two halves of an m-tile are ADJACENT in
// schedule order, so half 1's A reads hit L2 lines fetched by half 0.
// Half 0 -> g_X1 fp32 (+b1). Half 1 -> bf16 X2 + fp16 lat copy into g_pair.
// ---------------------------------------------------------------------------
#define GBK 16
#define APAD 20    // u32 per A row (16 + 4)
#define BPAD 136   // u32 per B row (128 + 8)

__global__ __launch_bounds__(256, 2) void mlp1_gemm_mma(const float* __restrict__ lat,
                                                        const float* __restrict__ W1,
                                                        const float* __restrict__ b1) {
    const int half = blockIdx.x;
    const float* __restrict__ Bsrc = W1 + (half ? (DIM * DIM) : 0); // [k][n] row-major
    const int m0 = blockIdx.y * 128;
    const u64 pol = make_evict_last_policy();

    __shared__ uint32_t Asm[2][128][APAD];
    __shared__ uint32_t Bsm[2][GBK][BPAD];
    __shared__ float    sb1[DIM];

    const int tid   = threadIdx.x;
    const int wid   = tid >> 5;
    const int lane  = tid & 31;
    const int warpm = (wid >> 2) * 64;   // 0 or 64
    const int warpn = (wid & 3) * 32;    // 0,32,64,96
    const int r     = lane >> 2;         // 0..7
    const int c     = lane & 3;          // 0..3

    if (tid < DIM) sb1[tid] = b1[tid];

    // Fixed per-thread load coordinates.
    const int a_row = tid >> 2;              // 0..63
    const int a_cq  = (tid & 3) * 4;         // 0,4,8,12
    int a_gm0 = m0 + a_row;       if (a_gm0 >= N_NODES) a_gm0 = N_NODES - 1;
    int a_gm1 = m0 + a_row + 64;  if (a_gm1 >= N_NODES) a_gm1 = N_NODES - 1;
    const int b_kr = tid >> 5;               // 0..7
    const int b_cq = (tid & 31) * 4;         // 0..124

    float acc[4][4][4];
#pragma unroll
    for (int tm = 0; tm < 4; tm++)
#pragma unroll
        for (int tn = 0; tn < 4; tn++)
#pragma unroll
            for (int q = 0; q < 4; q++) acc[tm][tn][q] = 0.f;

    float4 va0, va1, vb0, vb1;                 // prefetch registers

    auto prefetch = [&](int k0) {
        va0 = ldg_keep(lat + (size_t)a_gm0 * DIM + k0 + a_cq, pol);
        va1 = ldg_keep(lat + (size_t)a_gm1 * DIM + k0 + a_cq, pol);
        vb0 = *(const float4*)(Bsrc + (size_t)(k0 + b_kr) * DIM + b_cq);
        vb1 = *(const float4*)(Bsrc + (size_t)(k0 + 8 + b_kr) * DIM + b_cq);
    };
    auto commit = [&](int buf, int k0) {
        if (half) {
            // fp16 latents copy into g_pair [256,512): dims k0+a_cq .. +3.
            const int d0 = k0 + a_cq;
            __half2 lo, hi; uint2 w;
            lo = __floats2half2_rn(va0.x, va0.y); hi = __floats2half2_rn(va0.z, va0.w);
            w.x = *(uint32_t*)&lo; w.y = *(uint32_t*)&hi;
            *(uint2*)(&g_pair[(size_t)a_gm0 * 128 + 64 + (d0 >> 1)]) = w;
            lo = __floats2half2_rn(va1.x, va1.y); hi = __floats2half2_rn(va1.z, va1.w);
            w.x = *(uint32_t*)&lo; w.y = *(uint32_t*)&hi;
            *(uint2*)(&g_pair[(size_t)a_gm1 * 128 + 64 + (d0 >> 1)]) = w;
        }
        uint4 t;
        t.x = f2tf32(va0.x); t.y = f2tf32(va0.y); t.z = f2tf32(va0.z); t.w = f2tf32(va0.w);
        *(uint4*)(&Asm[buf][a_row][a_cq]) = t;
        t.x = f2tf32(va1.x); t.y = f2tf32(va1.y); t.z = f2tf32(va1.z); t.w = f2tf32(va1.w);
        *(uint4*)(&Asm[buf][a_row + 64][a_cq]) = t;
        t.x = f2tf32(vb0.x); t.y = f2tf32(vb0.y); t.z = f2tf32(vb0.z); t.w = f2tf32(vb0.w);
        *(uint4*)(&Bsm[buf][b_kr][b_cq]) = t;
        t.x = f2tf32(vb1.x); t.y = f2tf32(vb1.y); t.z = f2tf32(vb1.z); t.w = f2tf32(vb1.w);
        *(uint4*)(&Bsm[buf][b_kr + 8][b_cq]) = t;
    };

    prefetch(0);
    commit(0, 0);
    __syncthreads();

    int s = 0;
    for (int k0 = 0; k0 < DIM; k0 += GBK, s ^= 1) {
        const bool more = (k0 + GBK) < DIM;
        if (more) prefetch(k0 + GBK);        // LDG latency hides under mainloop

#pragma unroll
        for (int ch = 0; ch < 2; ch++) {
            const int kc = ch * 8;
            uint32_t af[4][4];
#pragma unroll
            for (int tm = 0; tm < 4; tm++) {
                const int mr = warpm + tm * 16;
                af[tm][0] = Asm[s][mr + r    ][kc + c];
                af[tm][1] = Asm[s][mr + r + 8][kc + c];
                af[tm][2] = Asm[s][mr + r    ][kc + c + 4];
                af[tm][3] = Asm[s][mr + r + 8][kc + c + 4];
            }
            uint32_t bf[4][2];
#pragma unroll
            for (int tn = 0; tn < 4; tn++) {
                const int nc = warpn + tn * 8;
                bf[tn][0] = Bsm[s][kc + c    ][nc + r];
                bf[tn][1] = Bsm[s][kc + c + 4][nc + r];
            }
#pragma unroll
            for (int tm = 0; tm < 4; tm++)
#pragma unroll
                for (int tn = 0; tn < 4; tn++)
                    mma_tf32(acc[tm][tn], af[tm], bf[tn]);
        }

        if (more) commit(s ^ 1, k0 + GBK);
        __syncthreads();
    }

    // Epilogue. C frag: c0,c1 @ (row=r, col=2c,2c+1); c2,c3 @ (row=r+8).
    if (half == 0) {
#pragma unroll
        for (int tm = 0; tm < 4; tm++) {
            const int gmA = m0 + warpm + tm * 16 + r;
            const int gmB = gmA + 8;
#pragma unroll
            for (int tn = 0; tn < 4; tn++) {
                const int nc = warpn + tn * 8 + 2 * c;
                const float bx = sb1[nc], by = sb1[nc + 1];
                if (gmA < N_NODES) {
                    float2 v = make_float2(acc[tm][tn][0] + bx, acc[tm][tn][1] + by);
                    *(float2*)(g_X1 + (size_t)gmA * DIM + nc) = v;
                }
                if (gmB < N_NODES) {
                    float2 v = make_float2(acc[tm][tn][2] + bx, acc[tm][tn][3] + by);
                    *(float2*)(g_X1 + (size_t)gmB * DIM + nc) = v;
                }
            }
        }
    } else {
#pragma unroll
        for (int tm = 0; tm < 4; tm++) {
            const int gmA = m0 + warpm + tm * 16 + r;
            const int gmB = gmA + 8;
#pragma unroll
            for (int tn = 0; tn < 4; tn++) {
                const int nc = warpn + tn * 8 + 2 * c;
                if (gmA < N_NODES) {
                    __nv_bfloat162 h = __floats2bfloat162_rn(acc[tm][tn][0], acc[tm][tn][1]);
                    g_pair[(size_t)gmA * 128 + (nc >> 1)] = *(uint32_t*)&h;
                }
                if (gmB < N_NODES) {
                    __nv_bfloat162 h = __floats2bfloat162_rn(acc[tm][tn][2], acc[tm][tn][3]);
                    g_pair[(size_t)gmB * 128 + (nc >> 1)] = *(uint32_t*)&h;
                }
            }
        }
    }
}

// ---------------------------------------------------------------------------
// Kernel 2: HALF-WARP per node, two-phase softmax, register-lean.
// - Neighbor indices re-loaded per phase (nbr row L1-hot in phase B): no ro[16].
// - No max-subtraction: scores are O(1) here (sum of 128 small relu terms),
//   exp2 overflow needs |s|>127 — softmax is shift-invariant so result is
//   identical; saves the max-tree and 16 subs.
// ---------------------------------------------------------------------------
__global__ __launch_bounds__(128) void attend_kernel(const int* __restrict__ nbr,
                                                     const float* __restrict__ W2,
                                                     float* __restrict__ out) {
    __shared__ float s_w2[DIM];
    const int tid = threadIdx.x;
    s_w2[tid] = W2[tid] * 1.4426950408889634f;   // fold log2e: exp(s) = exp2(s')
    __syncthreads();

    const int n = blockIdx.x * 8 + (tid >> 4);   // node per half-warp (exact: 100000/8)
    const int sl = tid & 15;                     // sub-lane: dims sl*8..sl*8+7
    const u64 pol = make_evict_last_policy();

    const float4 x1a = __ldcs((const float4*)(g_X1 + (size_t)n * DIM + sl * 8));
    const float4 x1b = __ldcs((const float4*)(g_X1 + (size_t)n * DIM + sl * 8 + 4));
    const float4 w2a = *(const float4*)(s_w2 + sl * 8);
    const float4 w2b = *(const float4*)(s_w2 + sl * 8 + 4);

    const uint32_t sl4 = (uint32_t)sl << 2;

    // Phase A: scores (exp2-domain, unnormalized).
    float sc[KNB];
    float rz = 0.f;
#pragma unroll
    for (int g = 0; g < 4; g++) {
        const int4 jv = __ldg((const int4*)(nbr + (size_t)n * KNB + g * 4));
        uint4 xq[4];
        xq[0] = ldg_keep4u(g_pair + (((uint32_t)jv.x << 7) + sl4), pol);
        xq[1] = ldg_keep4u(g_pair + (((uint32_t)jv.y << 7) + sl4), pol);
        xq[2] = ldg_keep4u(g_pair + (((uint32_t)jv.z << 7) + sl4), pol);
        xq[3] = ldg_keep4u(g_pair + (((uint32_t)jv.w << 7) + sl4), pol);

        float p[4];
#pragma unroll
        for (int t = 0; t < 4; t++) {
            const float2 a0 = __bfloat1622float2(*(const __nv_bfloat162*)&xq[t].x);
            const float2 a1 = __bfloat1622float2(*(const __nv_bfloat162*)&xq[t].y);
            const float2 a2 = __bfloat1622float2(*(const __nv_bfloat162*)&xq[t].z);
            const float2 a3 = __bfloat1622float2(*(const __nv_bfloat162*)&xq[t].w);
            float s = fmaxf(x1a.x + a0.x, 0.f) * w2a.x;
            s = fmaf(fmaxf(x1a.y + a0.y, 0.f), w2a.y, s);
            s = fmaf(fmaxf(x1a.z + a1.x, 0.f), w2a.z, s);
            s = fmaf(fmaxf(x1a.w + a1.y, 0.f), w2a.w, s);
            s = fmaf(fmaxf(x1b.x + a2.x, 0.f), w2b.x, s);
            s = fmaf(fmaxf(x1b.y + a2.y, 0.f), w2b.y, s);
            s = fmaf(fmaxf(x1b.z + a3.x, 0.f), w2b.z, s);
            s = fmaf(fmaxf(x1b.w + a3.y, 0.f), w2b.w, s);
            p[t] = s;
        }
#pragma unroll
        for (int d = 8; d > 0; d >>= 1) {
            p[0] += __shfl_xor_sync(0xffffffffu, p[0], d);
            p[1] += __shfl_xor_sync(0xffffffffu, p[1], d);
            p[2] += __shfl_xor_sync(0xffffffffu, p[2], d);
            p[3] += __shfl_xor_sync(0xffffffffu, p[3], d);
        }
#pragma unroll
        for (int t = 0; t < 4; t++) {
            const float e = exp2f(p[t]);
            sc[g * 4 + t] = e;
            rz += e;
        }
    }

    const float inv = 1.f / rz;
#pragma unroll
    for (int k = 0; k < KNB; k++) sc[k] *= inv;

    // Phase B: weighted accumulate over fp16 lat halves (nbr rows L1-hot).
    float acc[8];
#pragma unroll
    for (int i = 0; i < 8; i++) acc[i] = 0.f;

#pragma unroll
    for (int g = 0; g < 4; g++) {
        const int4 jv = __ldg((const int4*)(nbr + (size_t)n * KNB + g * 4));
        uint4 lq[4];
        lq[0] = ldg_keep4u(g_pair + (((uint32_t)jv.x << 7) + sl4) + 64, pol);
        lq[1] = ldg_keep4u(g_pair + (((uint32_t)jv.y << 7) + sl4) + 64, pol);
        lq[2] = ldg_keep4u(g_pair + (((uint32_t)jv.z << 7) + sl4) + 64, pol);
        lq[3] = ldg_keep4u(g_pair + (((uint32_t)jv.w << 7) + sl4) + 64, pol);
#pragma unroll
        for (int t = 0; t < 4; t++) {
            const float2 l0 = __half22float2(*(const __half2*)&lq[t].x);
            const float2 l1 = __half22float2(*(const __half2*)&lq[t].y);
            const float2 l2 = __half22float2(*(const __half2*)&lq[t].z);
            const float2 l3 = __half22float2(*(const __half2*)&lq[t].w);
            const float w = sc[g * 4 + t];
            acc[0] = fmaf(w, l0.x, acc[0]);
            acc[1] = fmaf(w, l0.y, acc[1]);
            acc[2] = fmaf(w, l1.x, acc[2]);
            acc[3] = fmaf(w, l1.y, acc[3]);
            acc[4] = fmaf(w, l2.x, acc[4]);
            acc[5] = fmaf(w, l2.y, acc[5]);
            acc[6] = fmaf(w, l3.x, acc[6]);
            acc[7] = fmaf(w, l3.y, acc[7]);
        }
    }

    float4 o0, o1;
    o0.x = acc[0]; o0.y = acc[1]; o0.z = acc[2]; o0.w = acc[3];
    o1.x = acc[4]; o1.y = acc[5]; o1.z = acc[6]; o1.w = acc[7];
    __stcs((float4*)(out + (size_t)n * DIM + sl * 8), o0);
    __stcs((float4*)(out + (size_t)n * DIM + sl * 8 + 4), o1);
}

// ---------------------------------------------------------------------------
// Launch
// ---------------------------------------------------------------------------
extern "C" void kernel_launch(void* const* d_in, const int* in_sizes, int n_in,
                              void* d_out, int out_size) {
    const float* latents   = (const float*)d_in[0];
    const int*   neighbors = (const int*)d_in[1];   // int32 (JAX x64-disabled)
    const float* W1        = (const float*)d_in[2];
    const float* b1        = (const float*)d_in[3];
    const float* W2        = (const float*)d_in[4];
    // d_in[5] = b2: cancels in softmax.
    float* out = (float*)d_out;

    (void)in_sizes; (void)n_in; (void)out_size;

    dim3 ggrid(2, (N_NODES + 127) / 128);   // halves adjacent -> A reads L2-paired
    mlp1_gemm_mma<<<ggrid, 256>>>(latents, W1, b1);

    const int blocks = N_NODES / 8;   // 12500, exact: 8 nodes (half-warps) per block
    attend_kernel<<<blocks, 128>>>(neighbors, W2, out);
}

// round 15
// speedup vs baseline: 2.7532x; 1.0077x over previous
#include <cuda_runtime.h>
#include <cuda_bf16.h>
#include <cuda_fp16.h>
#include <cstdint>

#define N_NODES 100000
#define DIM     128
#define KNB     16

// Scratch tables.
__device__ float g_X1[(size_t)N_NODES * DIM];
// g_pair: fused gather table, 512 B per row j:
//   bytes [0,256):   128 x bf16  X2[j]
//   bytes [256,512): 128 x fp16  lat[j]
__device__ uint32_t g_pair[(size_t)N_NODES * 128];

typedef unsigned long long u64;

// ---- cache-policy loads ------------------------------------------------------
__device__ __forceinline__ u64 make_evict_last_policy() {
    u64 pol;
    asm("createpolicy.fractional.L2::evict_last.b64 %0, 1.0;" : "=l"(pol));
    return pol;
}
__device__ __forceinline__ float4 ldg_keep(const float* p, u64 pol) {
    float4 v;
    asm("ld.global.nc.L2::cache_hint.v4.f32 {%0,%1,%2,%3}, [%4], %5;"
        : "=f"(v.x), "=f"(v.y), "=f"(v.z), "=f"(v.w) : "l"(p), "l"(pol));
    return v;
}
__device__ __forceinline__ uint4 ldg_keep4u(const uint32_t* p, u64 pol) {
    uint4 v;
    asm("ld.global.nc.L2::cache_hint.v4.b32 {%0,%1,%2,%3}, [%4], %5;"
        : "=r"(v.x), "=r"(v.y), "=r"(v.z), "=r"(v.w) : "l"(p), "l"(pol));
    return v;
}

// ---- tf32 helpers --------------------------------------------------------------
__device__ __forceinline__ uint32_t f2tf32(float x) {
    uint32_t r;
    asm("cvt.rna.tf32.f32 %0, %1;" : "=r"(r) : "f"(x));
    return r;
}
__device__ __forceinline__ void mma_tf32(float* d, const uint32_t* a, const uint32_t* b) {
    asm volatile(
        "mma.sync.aligned.m16n8k8.row.col.f32.tf32.tf32.f32 "
        "{%0,%1,%2,%3}, {%4,%5,%6,%7}, {%8,%9}, {%0,%1,%2,%3};"
        : "+f"(d[0]), "+f"(d[1]), "+f"(d[2]), "+f"(d[3])
        : "r"(a[0]), "r"(a[1]), "r"(a[2]), "r"(a[3]), "r"(b[0]), "r"(b[1]));
}

// ---------------------------------------------------------------------------
// Kernel 1: FUSED-HALVES tf32 GEMM. One CTA per 128-row m-tile:
//   - loads full A tile (128 x K=128, tf32) into smem ONCE (+ fp16 lat copy),
//   - runs the N=128 mainloop twice (B = W1 half 0, then half 1),
//   - 16 pipelined B stages; half-0 epilogue overlaps half-1 B prefetch.
// Dynamic smem: A full (128x132 u32) + B dbl-buffer (2x16x136 u32) + bias.
// ---------------------------------------------------------------------------
#define APAD 132                       // u32 per full-A row (128 + 4)
#define BPAD 136                       // u32 per B row (128 + 8)
#define SM_A_BYTES   (128 * APAD * 4)                 // 67584
#define SM_B_BYTES   (2 * 16 * BPAD * 4)              // 17408
#define SM_B_OFF     SM_A_BYTES
#define SM_B1_OFF    (SM_A_BYTES + SM_B_BYTES)
#define SM_TOTAL     (SM_B1_OFF + 512)

__global__ __launch_bounds__(256, 2) void mlp1_gemm_mma(const float* __restrict__ lat,
                                                        const float* __restrict__ W1,
                                                        const float* __restrict__ b1) {
    extern __shared__ __align__(16) char smem[];
    uint32_t (*Asm)[APAD]     = (uint32_t(*)[APAD])smem;
    uint32_t (*Bsm)[16][BPAD] = (uint32_t(*)[16][BPAD])(smem + SM_B_OFF);
    float*    sb1             = (float*)(smem + SM_B1_OFF);

    const int m0 = blockIdx.x * 128;
    const u64 pol = make_evict_last_policy();

    const int tid   = threadIdx.x;
    const int wid   = tid >> 5;
    const int lane  = tid & 31;
    const int warpm = (wid >> 2) * 64;   // 0 or 64
    const int warpn = (wid & 3) * 32;    // 0,32,64,96
    const int r     = lane >> 2;         // 0..7
    const int c     = lane & 3;          // 0..3

    if (tid < DIM) sb1[tid] = b1[tid];

    // B-load coords (per stage: 2 float4/thread).
    const int b_kr = tid >> 5;               // 0..7
    const int b_cq = (tid & 31) * 4;         // 0..124

    float4 vb0, vb1;
    // Stage t (0..15): half = t>>3, k0 = (t&7)*16.
    auto prefetchB = [&](int t) {
        const float* Bs = W1 + (size_t)(t >> 3) * (DIM * DIM) + (size_t)((t & 7) * 16) * DIM;
        vb0 = *(const float4*)(Bs + (size_t)b_kr * DIM + b_cq);
        vb1 = *(const float4*)(Bs + (size_t)(b_kr + 8) * DIM + b_cq);
    };
    auto commitB = [&](int buf) {
        uint4 t;
        t.x = f2tf32(vb0.x); t.y = f2tf32(vb0.y); t.z = f2tf32(vb0.z); t.w = f2tf32(vb0.w);
        *(uint4*)(&Bsm[buf][b_kr][b_cq]) = t;
        t.x = f2tf32(vb1.x); t.y = f2tf32(vb1.y); t.z = f2tf32(vb1.z); t.w = f2tf32(vb1.w);
        *(uint4*)(&Bsm[buf][b_kr + 8][b_cq]) = t;
    };

    prefetchB(0);

    // Full A tile load: 4096 float4 / 256 thr = 16 each. Also emits the fp16
    // latents copy into g_pair [256,512) (read-once, write-once).
#pragma unroll 4
    for (int i = 0; i < 16; i++) {
        const int f   = i * 256 + tid;
        const int row = f >> 5;              // 0..127
        const int cq  = (f & 31) * 4;        // 0..124
        int gm = m0 + row;
        if (gm >= N_NODES) gm = N_NODES - 1;
        float4 v = ldg_keep(lat + (size_t)gm * DIM + cq, pol);
        __half2 lo = __floats2half2_rn(v.x, v.y);
        __half2 hi = __floats2half2_rn(v.z, v.w);
        uint2 w;
        w.x = *(uint32_t*)&lo;
        w.y = *(uint32_t*)&hi;
        *(uint2*)(&g_pair[(size_t)gm * 128 + 64 + (cq >> 1)]) = w;
        uint4 t;
        t.x = f2tf32(v.x); t.y = f2tf32(v.y); t.z = f2tf32(v.z); t.w = f2tf32(v.w);
        *(uint4*)(&Asm[row][cq]) = t;
    }
    commitB(0);
    __syncthreads();

    float acc[4][4][4];
#pragma unroll
    for (int tm = 0; tm < 4; tm++)
#pragma unroll
        for (int tn = 0; tn < 4; tn++)
#pragma unroll
            for (int q = 0; q < 4; q++) acc[tm][tn][q] = 0.f;

    // Epilogues (acc in registers; no smem deps).
    auto epilogue = [&](int half) {
#pragma unroll
        for (int tm = 0; tm < 4; tm++) {
            const int gmA = m0 + warpm + tm * 16 + r;
            const int gmB = gmA + 8;
#pragma unroll
            for (int tn = 0; tn < 4; tn++) {
                const int nc = warpn + tn * 8 + 2 * c;
                if (half == 0) {
                    const float bx = sb1[nc], by = sb1[nc + 1];
                    if (gmA < N_NODES) {
                        float2 v = make_float2(acc[tm][tn][0] + bx, acc[tm][tn][1] + by);
                        *(float2*)(g_X1 + (size_t)gmA * DIM + nc) = v;
                    }
                    if (gmB < N_NODES) {
                        float2 v = make_float2(acc[tm][tn][2] + bx, acc[tm][tn][3] + by);
                        *(float2*)(g_X1 + (size_t)gmB * DIM + nc) = v;
                    }
                } else {
                    if (gmA < N_NODES) {
                        __nv_bfloat162 h = __floats2bfloat162_rn(acc[tm][tn][0], acc[tm][tn][1]);
                        g_pair[(size_t)gmA * 128 + (nc >> 1)] = *(uint32_t*)&h;
                    }
                    if (gmB < N_NODES) {
                        __nv_bfloat162 h = __floats2bfloat162_rn(acc[tm][tn][2], acc[tm][tn][3]);
                        g_pair[(size_t)gmB * 128 + (nc >> 1)] = *(uint32_t*)&h;
                    }
                }
            }
        }
    };

    for (int t = 0; t < 16; t++) {
        const bool more = (t < 15);
        if (more) prefetchB(t + 1);

        const int kb = (t & 7) * 16;
        const int buf = t & 1;
#pragma unroll
        for (int ch = 0; ch < 2; ch++) {
            const int kc = ch * 8;              // local within stage
            const int kg = kb + kc;             // global K within Asm row
            uint32_t af[4][4];
#pragma unroll
            for (int tm = 0; tm < 4; tm++) {
                const int mr = warpm + tm * 16;
                af[tm][0] = Asm[mr + r    ][kg + c];
                af[tm][1] = Asm[mr + r + 8][kg + c];
                af[tm][2] = Asm[mr + r    ][kg + c + 4];
                af[tm][3] = Asm[mr + r + 8][kg + c + 4];
            }
            uint32_t bf[4][2];
#pragma unroll
            for (int tn = 0; tn < 4; tn++) {
                const int nc = warpn + tn * 8;
                bf[tn][0] = Bsm[buf][kc + c    ][nc + r];
                bf[tn][1] = Bsm[buf][kc + c + 4][nc + r];
            }
#pragma unroll
            for (int tm = 0; tm < 4; tm++)
#pragma unroll
                for (int tn = 0; tn < 4; tn++)
                    mma_tf32(acc[tm][tn], af[tm], bf[tn]);
        }

        if (more) commitB((t + 1) & 1);
        __syncthreads();

        if (t == 7) {
            epilogue(0);                        // overlaps half-1 B pipeline
#pragma unroll
            for (int tm = 0; tm < 4; tm++)
#pragma unroll
                for (int tn = 0; tn < 4; tn++)
#pragma unroll
                    for (int q = 0; q < 4; q++) acc[tm][tn][q] = 0.f;
        }
    }
    epilogue(1);
}

// ---------------------------------------------------------------------------
// Kernel 2: HALF-WARP per node, two-phase softmax, register-lean (unchanged
// from the measured 83.5 us config).
// ---------------------------------------------------------------------------
__global__ __launch_bounds__(128) void attend_kernel(const int* __restrict__ nbr,
                                                     const float* __restrict__ W2,
                                                     float* __restrict__ out) {
    __shared__ float s_w2[DIM];
    const int tid = threadIdx.x;
    s_w2[tid] = W2[tid] * 1.4426950408889634f;   // fold log2e: exp(s) = exp2(s')
    __syncthreads();

    const int n = blockIdx.x * 8 + (tid >> 4);   // node per half-warp (exact: 100000/8)
    const int sl = tid & 15;                     // sub-lane: dims sl*8..sl*8+7
    const u64 pol = make_evict_last_policy();

    const float4 x1a = __ldcs((const float4*)(g_X1 + (size_t)n * DIM + sl * 8));
    const float4 x1b = __ldcs((const float4*)(g_X1 + (size_t)n * DIM + sl * 8 + 4));
    const float4 w2a = *(const float4*)(s_w2 + sl * 8);
    const float4 w2b = *(const float4*)(s_w2 + sl * 8 + 4);

    const uint32_t sl4 = (uint32_t)sl << 2;

    // Phase A: scores (exp2-domain, unnormalized; shift-invariance => no max
    // subtraction needed at this score scale).
    float sc[KNB];
    float rz = 0.f;
#pragma unroll
    for (int g = 0; g < 4; g++) {
        const int4 jv = __ldg((const int4*)(nbr + (size_t)n * KNB + g * 4));
        uint4 xq[4];
        xq[0] = ldg_keep4u(g_pair + (((uint32_t)jv.x << 7) + sl4), pol);
        xq[1] = ldg_keep4u(g_pair + (((uint32_t)jv.y << 7) + sl4), pol);
        xq[2] = ldg_keep4u(g_pair + (((uint32_t)jv.z << 7) + sl4), pol);
        xq[3] = ldg_keep4u(g_pair + (((uint32_t)jv.w << 7) + sl4), pol);

        float p[4];
#pragma unroll
        for (int t = 0; t < 4; t++) {
            const float2 a0 = __bfloat1622float2(*(const __nv_bfloat162*)&xq[t].x);
            const float2 a1 = __bfloat1622float2(*(const __nv_bfloat162*)&xq[t].y);
            const float2 a2 = __bfloat1622float2(*(const __nv_bfloat162*)&xq[t].z);
            const float2 a3 = __bfloat1622float2(*(const __nv_bfloat162*)&xq[t].w);
            float s = fmaxf(x1a.x + a0.x, 0.f) * w2a.x;
            s = fmaf(fmaxf(x1a.y + a0.y, 0.f), w2a.y, s);
            s = fmaf(fmaxf(x1a.z + a1.x, 0.f), w2a.z, s);
            s = fmaf(fmaxf(x1a.w + a1.y, 0.f), w2a.w, s);
            s = fmaf(fmaxf(x1b.x + a2.x, 0.f), w2b.x, s);
            s = fmaf(fmaxf(x1b.y + a2.y, 0.f), w2b.y, s);
            s = fmaf(fmaxf(x1b.z + a3.x, 0.f), w2b.z, s);
            s = fmaf(fmaxf(x1b.w + a3.y, 0.f), w2b.w, s);
            p[t] = s;
        }
#pragma unroll
        for (int d = 8; d > 0; d >>= 1) {
            p[0] += __shfl_xor_sync(0xffffffffu, p[0], d);
            p[1] += __shfl_xor_sync(0xffffffffu, p[1], d);
            p[2] += __shfl_xor_sync(0xffffffffu, p[2], d);
            p[3] += __shfl_xor_sync(0xffffffffu, p[3], d);
        }
#pragma unroll
        for (int t = 0; t < 4; t++) {
            const float e = exp2f(p[t]);
            sc[g * 4 + t] = e;
            rz += e;
        }
    }

    const float inv = 1.f / rz;
#pragma unroll
    for (int k = 0; k < KNB; k++) sc[k] *= inv;

    // Phase B: weighted accumulate over fp16 lat halves (nbr rows L1-hot).
    float acc[8];
#pragma unroll
    for (int i = 0; i < 8; i++) acc[i] = 0.f;

#pragma unroll
    for (int g = 0; g < 4; g++) {
        const int4 jv = __ldg((const int4*)(nbr + (size_t)n * KNB + g * 4));
        uint4 lq[4];
        lq[0] = ldg_keep4u(g_pair + (((uint32_t)jv.x << 7) + sl4) + 64, pol);
        lq[1] = ldg_keep4u(g_pair + (((uint32_t)jv.y << 7) + sl4) + 64, pol);
        lq[2] = ldg_keep4u(g_pair + (((uint32_t)jv.z << 7) + sl4) + 64, pol);
        lq[3] = ldg_keep4u(g_pair + (((uint32_t)jv.w << 7) + sl4) + 64, pol);
#pragma unroll
        for (int t = 0; t < 4; t++) {
            const float2 l0 = __half22float2(*(const __half2*)&lq[t].x);
            const float2 l1 = __half22float2(*(const __half2*)&lq[t].y);
            const float2 l2 = __half22float2(*(const __half2*)&lq[t].z);
            const float2 l3 = __half22float2(*(const __half2*)&lq[t].w);
            const float w = sc[g * 4 + t];
            acc[0] = fmaf(w, l0.x, acc[0]);
            acc[1] = fmaf(w, l0.y, acc[1]);
            acc[2] = fmaf(w, l1.x, acc[2]);
            acc[3] = fmaf(w, l1.y, acc[3]);
            acc[4] = fmaf(w, l2.x, acc[4]);
            acc[5] = fmaf(w, l2.y, acc[5]);
            acc[6] = fmaf(w, l3.x, acc[6]);
            acc[7] = fmaf(w, l3.y, acc[7]);
        }
    }

    float4 o0, o1;
    o0.x = acc[0]; o0.y = acc[1]; o0.z = acc[2]; o0.w = acc[3];
    o1.x = acc[4]; o1.y = acc[5]; o1.z = acc[6]; o1.w = acc[7];
    __stcs((float4*)(out + (size_t)n * DIM + sl * 8), o0);
    __stcs((float4*)(out + (size_t)n * DIM + sl * 8 + 4), o1);
}

// ---------------------------------------------------------------------------
// Launch
// ---------------------------------------------------------------------------
extern "C" void kernel_launch(void* const* d_in, const int* in_sizes, int n_in,
                              void* d_out, int out_size) {
    const float* latents   = (const float*)d_in[0];
    const int*   neighbors = (const int*)d_in[1];   // int32 (JAX x64-disabled)
    const float* W1        = (const float*)d_in[2];
    const float* b1        = (const float*)d_in[3];
    const float* W2        = (const float*)d_in[4];
    // d_in[5] = b2: cancels in softmax.
    float* out = (float*)d_out;

    (void)in_sizes; (void)n_in; (void)out_size;

    static bool attr_done = false;
    if (!attr_done) {
        cudaFuncSetAttribute(mlp1_gemm_mma,
                             cudaFuncAttributeMaxDynamicSharedMemorySize, SM_TOTAL);
        attr_done = true;
    }

    const int gemm_blocks = (N_NODES + 127) / 128;   // 782
    mlp1_gemm_mma<<<gemm_blocks, 256, SM_TOTAL>>>(latents, W1, b1);

    const int blocks = N_NODES / 8;   // 12500, exact: 8 nodes (half-warps) per block
    attend_kernel<<<blocks, 128>>>(neighbors, W2, out);
}

// round 16
// speedup vs baseline: 3.0177x; 1.0961x over previous
#include <cuda_runtime.h>
#include <cuda_bf16.h>
#include <cuda_fp16.h>
#include <cstdint>

#define N_NODES 100000
#define DIM     128
#define KNB     16

// Scratch tables.
__device__ float g_X1[(size_t)N_NODES * DIM];
// g_pair: fused gather table, 512 B per row j:
//   bytes [0,256):   128 x bf16  X2[j]
//   bytes [256,512): 128 x fp16  lat[j]
__device__ uint32_t g_pair[(size_t)N_NODES * 128];

typedef unsigned long long u64;

// ---- cache-policy loads ------------------------------------------------------
__device__ __forceinline__ u64 make_evict_last_policy() {
    u64 pol;
    asm("createpolicy.fractional.L2::evict_last.b64 %0, 1.0;" : "=l"(pol));
    return pol;
}
__device__ __forceinline__ float4 ldg_keep(const float* p, u64 pol) {
    float4 v;
    asm("ld.global.nc.L2::cache_hint.v4.f32 {%0,%1,%2,%3}, [%4], %5;"
        : "=f"(v.x), "=f"(v.y), "=f"(v.z), "=f"(v.w) : "l"(p), "l"(pol));
    return v;
}
__device__ __forceinline__ uint4 ldg_keep4u(const uint32_t* p, u64 pol) {
    uint4 v;
    asm("ld.global.nc.L2::cache_hint.v4.b32 {%0,%1,%2,%3}, [%4], %5;"
        : "=r"(v.x), "=r"(v.y), "=r"(v.z), "=r"(v.w) : "l"(p), "l"(pol));
    return v;
}

// ---- fp16 mma (m16n8k16): same 10-bit mantissa as tf32, 2x FLOP/issue --------
__device__ __forceinline__ void mma_f16(float* d, const uint32_t* a, const uint32_t* b) {
    asm volatile(
        "mma.sync.aligned.m16n8k16.row.col.f32.f16.f16.f32 "
        "{%0,%1,%2,%3}, {%4,%5,%6,%7}, {%8,%9}, {%0,%1,%2,%3};"
        : "+f"(d[0]), "+f"(d[1]), "+f"(d[2]), "+f"(d[3])
        : "r"(a[0]), "r"(a[1]), "r"(a[2]), "r"(a[3]), "r"(b[0]), "r"(b[1]));
}

// ---------------------------------------------------------------------------
// Kernel 1: FUSED-HALVES fp16 GEMM. One CTA per 128-row m-tile:
//   - loads full A tile (128 x 64 half2) into smem ONCE; the SAME half2 pairs
//     are the fp16 latents copy written to g_pair (one conversion, two uses),
//   - runs the N=128 mainloop twice (B = W1 half 0, then half 1),
//   - 16 pipelined B stages of K=16 (one m16n8k16 chunk each).
// A fragment (m16n8k16): a0/a1 = rows r,r+8 @ kpair c; a2/a3 @ kpair c+4.
// B fragment: b0 = kpair c @ col r; b1 = kpair c+4 @ col r.
// Static smem ~43 KB.
// ---------------------------------------------------------------------------
#define APAD 68    // u32 (half2) per A row (64 + 4)
#define BPAD 136   // u32 (half2) per B kpair row (128 + 8)

__global__ __launch_bounds__(256, 2) void mlp1_gemm_mma(const float* __restrict__ lat,
                                                        const float* __restrict__ W1,
                                                        const float* __restrict__ b1) {
    __shared__ uint32_t Asm[128][APAD];      // half2 pairs, full K
    __shared__ uint32_t Bsm[2][8][BPAD];     // half2 pairs, one K=16 stage per buf
    __shared__ float    sb1[DIM];

    const int m0 = blockIdx.x * 128;
    const u64 pol = make_evict_last_policy();

    const int tid   = threadIdx.x;
    const int wid   = tid >> 5;
    const int lane  = tid & 31;
    const int warpm = (wid >> 2) * 64;   // 0 or 64
    const int warpn = (wid & 3) * 32;    // 0,32,64,96
    const int r     = lane >> 2;         // 0..7
    const int c     = lane & 3;          // 0..3

    if (tid < DIM) sb1[tid] = b1[tid];

    // B-load coords: kpair kp = tid>>5 (0..7), cols nq..nq+3.
    const int b_kp = tid >> 5;
    const int b_nq = (tid & 31) * 4;

    float4 vb0, vb1;
    // Stage t (0..15): half = t>>3, k0 = (t&7)*16; rows 2kp, 2kp+1 of that slab.
    auto prefetchB = [&](int t) {
        const float* Bs = W1 + (size_t)(t >> 3) * (DIM * DIM) + (size_t)((t & 7) * 16) * DIM;
        vb0 = *(const float4*)(Bs + (size_t)(2 * b_kp) * DIM + b_nq);
        vb1 = *(const float4*)(Bs + (size_t)(2 * b_kp + 1) * DIM + b_nq);
    };
    auto commitB = [&](int buf) {
        __half2 h0 = __floats2half2_rn(vb0.x, vb1.x);
        __half2 h1 = __floats2half2_rn(vb0.y, vb1.y);
        __half2 h2 = __floats2half2_rn(vb0.z, vb1.z);
        __half2 h3 = __floats2half2_rn(vb0.w, vb1.w);
        uint4 t;
        t.x = *(uint32_t*)&h0;
        t.y = *(uint32_t*)&h1;
        t.z = *(uint32_t*)&h2;
        t.w = *(uint32_t*)&h3;
        *(uint4*)(&Bsm[buf][b_kp][b_nq]) = t;
    };

    prefetchB(0);

    // Full A tile load: 4096 float4 / 256 thr = 16 each. The half2 pairs are
    // BOTH the smem A operand and the fp16 latents copy in g_pair.
#pragma unroll 4
    for (int i = 0; i < 16; i++) {
        const int f   = i * 256 + tid;
        const int row = f >> 5;              // 0..127
        const int cq  = (f & 31) * 4;        // 0..124 (K cols)
        int gm = m0 + row;
        if (gm >= N_NODES) gm = N_NODES - 1;
        float4 v = ldg_keep(lat + (size_t)gm * DIM + cq, pol);
        __half2 lo = __floats2half2_rn(v.x, v.y);
        __half2 hi = __floats2half2_rn(v.z, v.w);
        uint2 w;
        w.x = *(uint32_t*)&lo;
        w.y = *(uint32_t*)&hi;
        *(uint2*)(&g_pair[(size_t)gm * 128 + 64 + (cq >> 1)]) = w;
        *(uint2*)(&Asm[row][cq >> 1]) = w;
    }
    commitB(0);
    __syncthreads();

    float acc[4][4][4];
#pragma unroll
    for (int tm = 0; tm < 4; tm++)
#pragma unroll
        for (int tn = 0; tn < 4; tn++)
#pragma unroll
            for (int q = 0; q < 4; q++) acc[tm][tn][q] = 0.f;

    // Epilogues (acc in registers; no smem deps).
    auto epilogue = [&](int half) {
#pragma unroll
        for (int tm = 0; tm < 4; tm++) {
            const int gmA = m0 + warpm + tm * 16 + r;
            const int gmB = gmA + 8;
#pragma unroll
            for (int tn = 0; tn < 4; tn++) {
                const int nc = warpn + tn * 8 + 2 * c;
                if (half == 0) {
                    const float bx = sb1[nc], by = sb1[nc + 1];
                    if (gmA < N_NODES) {
                        float2 v = make_float2(acc[tm][tn][0] + bx, acc[tm][tn][1] + by);
                        *(float2*)(g_X1 + (size_t)gmA * DIM + nc) = v;
                    }
                    if (gmB < N_NODES) {
                        float2 v = make_float2(acc[tm][tn][2] + bx, acc[tm][tn][3] + by);
                        *(float2*)(g_X1 + (size_t)gmB * DIM + nc) = v;
                    }
                } else {
                    if (gmA < N_NODES) {
                        __nv_bfloat162 h = __floats2bfloat162_rn(acc[tm][tn][0], acc[tm][tn][1]);
                        g_pair[(size_t)gmA * 128 + (nc >> 1)] = *(uint32_t*)&h;
                    }
                    if (gmB < N_NODES) {
                        __nv_bfloat162 h = __floats2bfloat162_rn(acc[tm][tn][2], acc[tm][tn][3]);
                        g_pair[(size_t)gmB * 128 + (nc >> 1)] = *(uint32_t*)&h;
                    }
                }
            }
        }
    };

    for (int t = 0; t < 16; t++) {
        const bool more = (t < 15);
        if (more) prefetchB(t + 1);

        const int kpb = (t & 7) * 8;            // kpair base within Asm row
        const int buf = t & 1;

        uint32_t af[4][4];
#pragma unroll
        for (int tm = 0; tm < 4; tm++) {
            const int mr = warpm + tm * 16;
            af[tm][0] = Asm[mr + r    ][kpb + c];
            af[tm][1] = Asm[mr + r + 8][kpb + c];
            af[tm][2] = Asm[mr + r    ][kpb + c + 4];
            af[tm][3] = Asm[mr + r + 8][kpb + c + 4];
        }
        uint32_t bf[4][2];
#pragma unroll
        for (int tn = 0; tn < 4; tn++) {
            const int nc = warpn + tn * 8;
            bf[tn][0] = Bsm[buf][c    ][nc + r];
            bf[tn][1] = Bsm[buf][c + 4][nc + r];
        }
#pragma unroll
        for (int tm = 0; tm < 4; tm++)
#pragma unroll
            for (int tn = 0; tn < 4; tn++)
                mma_f16(acc[tm][tn], af[tm], bf[tn]);

        if (more) commitB((t + 1) & 1);
        __syncthreads();

        if (t == 7) {
            epilogue(0);                        // overlaps half-1 B pipeline
#pragma unroll
            for (int tm = 0; tm < 4; tm++)
#pragma unroll
                for (int tn = 0; tn < 4; tn++)
#pragma unroll
                    for (int q = 0; q < 4; q++) acc[tm][tn][q] = 0.f;
        }
    }
    epilogue(1);
}

// ---------------------------------------------------------------------------
// Kernel 2: HALF-WARP per node, two-phase softmax, register-lean (unchanged
// from the measured 82.9 us config).
// ---------------------------------------------------------------------------
__global__ __launch_bounds__(128) void attend_kernel(const int* __restrict__ nbr,
                                                     const float* __restrict__ W2,
                                                     float* __restrict__ out) {
    __shared__ float s_w2[DIM];
    const int tid = threadIdx.x;
    s_w2[tid] = W2[tid] * 1.4426950408889634f;   // fold log2e: exp(s) = exp2(s')
    __syncthreads();

    const int n = blockIdx.x * 8 + (tid >> 4);   // node per half-warp (exact: 100000/8)
    const int sl = tid & 15;                     // sub-lane: dims sl*8..sl*8+7
    const u64 pol = make_evict_last_policy();

    const float4 x1a = __ldcs((const float4*)(g_X1 + (size_t)n * DIM + sl * 8));
    const float4 x1b = __ldcs((const float4*)(g_X1 + (size_t)n * DIM + sl * 8 + 4));
    const float4 w2a = *(const float4*)(s_w2 + sl * 8);
    const float4 w2b = *(const float4*)(s_w2 + sl * 8 + 4);

    const uint32_t sl4 = (uint32_t)sl << 2;

    // Phase A: scores (exp2-domain, unnormalized; shift-invariance => no max
    // subtraction needed at this score scale).
    float sc[KNB];
    float rz = 0.f;
#pragma unroll
    for (int g = 0; g < 4; g++) {
        const int4 jv = __ldg((const int4*)(nbr + (size_t)n * KNB + g * 4));
        uint4 xq[4];
        xq[0] = ldg_keep4u(g_pair + (((uint32_t)jv.x << 7) + sl4), pol);
        xq[1] = ldg_keep4u(g_pair + (((uint32_t)jv.y << 7) + sl4), pol);
        xq[2] = ldg_keep4u(g_pair + (((uint32_t)jv.z << 7) + sl4), pol);
        xq[3] = ldg_keep4u(g_pair + (((uint32_t)jv.w << 7) + sl4), pol);

        float p[4];
#pragma unroll
        for (int t = 0; t < 4; t++) {
            const float2 a0 = __bfloat1622float2(*(const __nv_bfloat162*)&xq[t].x);
            const float2 a1 = __bfloat1622float2(*(const __nv_bfloat162*)&xq[t].y);
            const float2 a2 = __bfloat1622float2(*(const __nv_bfloat162*)&xq[t].z);
            const float2 a3 = __bfloat1622float2(*(const __nv_bfloat162*)&xq[t].w);
            float s = fmaxf(x1a.x + a0.x, 0.f) * w2a.x;
            s = fmaf(fmaxf(x1a.y + a0.y, 0.f), w2a.y, s);
            s = fmaf(fmaxf(x1a.z + a1.x, 0.f), w2a.z, s);
            s = fmaf(fmaxf(x1a.w + a1.y, 0.f), w2a.w, s);
            s = fmaf(fmaxf(x1b.x + a2.x, 0.f), w2b.x, s);
            s = fmaf(fmaxf(x1b.y + a2.y, 0.f), w2b.y, s);
            s = fmaf(fmaxf(x1b.z + a3.x, 0.f), w2b.z, s);
            s = fmaf(fmaxf(x1b.w + a3.y, 0.f), w2b.w, s);
            p[t] = s;
        }
#pragma unroll
        for (int d = 8; d > 0; d >>= 1) {
            p[0] += __shfl_xor_sync(0xffffffffu, p[0], d);
            p[1] += __shfl_xor_sync(0xffffffffu, p[1], d);
            p[2] += __shfl_xor_sync(0xffffffffu, p[2], d);
            p[3] += __shfl_xor_sync(0xffffffffu, p[3], d);
        }
#pragma unroll
        for (int t = 0; t < 4; t++) {
            const float e = exp2f(p[t]);
            sc[g * 4 + t] = e;
            rz += e;
        }
    }

    const float inv = 1.f / rz;
#pragma unroll
    for (int k = 0; k < KNB; k++) sc[k] *= inv;

    // Phase B: weighted accumulate over fp16 lat halves (nbr rows L1-hot).
    float acc[8];
#pragma unroll
    for (int i = 0; i < 8; i++) acc[i] = 0.f;

#pragma unroll
    for (int g = 0; g < 4; g++) {
        const int4 jv = __ldg((const int4*)(nbr + (size_t)n * KNB + g * 4));
        uint4 lq[4];
        lq[0] = ldg_keep4u(g_pair + (((uint32_t)jv.x << 7) + sl4) + 64, pol);
        lq[1] = ldg_keep4u(g_pair + (((uint32_t)jv.y << 7) + sl4) + 64, pol);
        lq[2] = ldg_keep4u(g_pair + (((uint32_t)jv.z << 7) + sl4) + 64, pol);
        lq[3] = ldg_keep4u(g_pair + (((uint32_t)jv.w << 7) + sl4) + 64, pol);
#pragma unroll
        for (int t = 0; t < 4; t++) {
            const float2 l0 = __half22float2(*(const __half2*)&lq[t].x);
            const float2 l1 = __half22float2(*(const __half2*)&lq[t].y);
            const float2 l2 = __half22float2(*(const __half2*)&lq[t].z);
            const float2 l3 = __half22float2(*(const __half2*)&lq[t].w);
            const float w = sc[g * 4 + t];
            acc[0] = fmaf(w, l0.x, acc[0]);
            acc[1] = fmaf(w, l0.y, acc[1]);
            acc[2] = fmaf(w, l1.x, acc[2]);
            acc[3] = fmaf(w, l1.y, acc[3]);
            acc[4] = fmaf(w, l2.x, acc[4]);
            acc[5] = fmaf(w, l2.y, acc[5]);
            acc[6] = fmaf(w, l3.x, acc[6]);
            acc[7] = fmaf(w, l3.y, acc[7]);
        }
    }

    float4 o0, o1;
    o0.x = acc[0]; o0.y = acc[1]; o0.z = acc[2]; o0.w = acc[3];
    o1.x = acc[4]; o1.y = acc[5]; o1.z = acc[6]; o1.w = acc[7];
    __stcs((float4*)(out + (size_t)n * DIM + sl * 8), o0);
    __stcs((float4*)(out + (size_t)n * DIM + sl * 8 + 4), o1);
}

// ---------------------------------------------------------------------------
// Launch
// ---------------------------------------------------------------------------
extern "C" void kernel_launch(void* const* d_in, const int* in_sizes, int n_in,
                              void* d_out, int out_size) {
    const float* latents   = (const float*)d_in[0];
    const int*   neighbors = (const int*)d_in[1];   // int32 (JAX x64-disabled)
    const float* W1        = (const float*)d_in[2];
    const float* b1        = (const float*)d_in[3];
    const float* W2        = (const float*)d_in[4];
    // d_in[5] = b2: cancels in softmax.
    float* out = (float*)d_out;

    (void)in_sizes; (void)n_in; (void)out_size;

    const int gemm_blocks = (N_NODES + 127) / 128;   // 782
    mlp1_gemm_mma<<<gemm_blocks, 256>>>(latents, W1, b1);

    const int blocks = N_NODES / 8;   // 12500, exact: 8 nodes (half-warps) per block
    attend_kernel<<<blocks, 128>>>(neighbors, W2, out);
}

// round 17
// speedup vs baseline: 3.1106x; 1.0308x over previous
#include <cuda_runtime.h>
#include <cuda_bf16.h>
#include <cuda_fp16.h>
#include <cstdint>

#define N_NODES 100000
#define DIM     128
#define KNB     16

// Scratch tables.
__device__ float g_X1[(size_t)N_NODES * DIM];
// g_pair: fused gather table, 512 B per row j:
//   bytes [0,256):   128 x bf16  X2[j]
//   bytes [256,512): 128 x fp16  lat[j]
__device__ uint32_t g_pair[(size_t)N_NODES * 128];

typedef unsigned long long u64;

// ---- cache-policy loads ------------------------------------------------------
__device__ __forceinline__ u64 make_evict_last_policy() {
    u64 pol;
    asm("createpolicy.fractional.L2::evict_last.b64 %0, 1.0;" : "=l"(pol));
    return pol;
}
__device__ __forceinline__ float4 ldg_keep(const float* p, u64 pol) {
    float4 v;
    asm("ld.global.nc.L2::cache_hint.v4.f32 {%0,%1,%2,%3}, [%4], %5;"
        : "=f"(v.x), "=f"(v.y), "=f"(v.z), "=f"(v.w) : "l"(p), "l"(pol));
    return v;
}
__device__ __forceinline__ uint4 ldg_keep4u(const uint32_t* p, u64 pol) {
    uint4 v;
    asm("ld.global.nc.L2::cache_hint.v4.b32 {%0,%1,%2,%3}, [%4], %5;"
        : "=r"(v.x), "=r"(v.y), "=r"(v.z), "=r"(v.w) : "l"(p), "l"(pol));
    return v;
}

// ---- fp16 mma (m16n8k16): same 10-bit mantissa as tf32, 2x FLOP/issue --------
__device__ __forceinline__ void mma_f16(float* d, const uint32_t* a, const uint32_t* b) {
    asm volatile(
        "mma.sync.aligned.m16n8k16.row.col.f32.f16.f16.f32 "
        "{%0,%1,%2,%3}, {%4,%5,%6,%7}, {%8,%9}, {%0,%1,%2,%3};"
        : "+f"(d[0]), "+f"(d[1]), "+f"(d[2]), "+f"(d[3])
        : "r"(a[0]), "r"(a[1]), "r"(a[2]), "r"(a[3]), "r"(b[0]), "r"(b[1]));
}

// ---------------------------------------------------------------------------
// Kernel 1: BARRIER-FREE fp16 GEMM. One CTA per 128-row m-tile:
//   - prologue loads the FULL A tile (half2) AND ALL 16 B stages (both W1
//     halves, half2 kpairs) into 105 KB dynamic smem, emits fp16 lat copy,
//   - ONE __syncthreads, then 16 chunks x 16 mma with ZERO barriers/staging,
//   - half-0 epilogue at the K-sweep midpoint (registers only, no smem dep).
// Fragment indexing identical to the validated R16 mapping.
// ---------------------------------------------------------------------------
#define APAD 68    // u32 (half2) per A row (64 + 4)
#define BPAD 136   // u32 (half2) per B kpair row (128 + 8)
#define SM_A_BYTES  (128 * APAD * 4)          // 34816
#define SM_B_BYTES  (16 * 8 * BPAD * 4)       // 69632
#define SM_B_OFF    SM_A_BYTES
#define SM_SB1_OFF  (SM_A_BYTES + SM_B_BYTES)
#define SM_TOTAL    (SM_SB1_OFF + 512)        // ~105 KB

__global__ __launch_bounds__(256, 2) void mlp1_gemm_mma(const float* __restrict__ lat,
                                                        const float* __restrict__ W1,
                                                        const float* __restrict__ b1) {
    extern __shared__ __align__(16) char smem[];
    uint32_t (*Asm)[APAD]    = (uint32_t(*)[APAD])smem;
    uint32_t (*Bsm)[8][BPAD] = (uint32_t(*)[8][BPAD])(smem + SM_B_OFF);
    float*    sb1            = (float*)(smem + SM_SB1_OFF);

    const int m0 = blockIdx.x * 128;
    const u64 pol = make_evict_last_policy();

    const int tid   = threadIdx.x;
    const int wid   = tid >> 5;
    const int lane  = tid & 31;
    const int warpm = (wid >> 2) * 64;   // 0 or 64
    const int warpn = (wid & 3) * 32;    // 0,32,64,96
    const int r     = lane >> 2;         // 0..7
    const int c     = lane & 3;          // 0..3

    if (tid < DIM) sb1[tid] = b1[tid];

    // ---- Prologue: full A tile + fp16 lat copy --------------------------------
#pragma unroll 4
    for (int i = 0; i < 16; i++) {
        const int f   = i * 256 + tid;
        const int row = f >> 5;              // 0..127
        const int cq  = (f & 31) * 4;        // 0..124 (K cols)
        int gm = m0 + row;
        if (gm >= N_NODES) gm = N_NODES - 1;
        float4 v = ldg_keep(lat + (size_t)gm * DIM + cq, pol);
        __half2 lo = __floats2half2_rn(v.x, v.y);
        __half2 hi = __floats2half2_rn(v.z, v.w);
        uint2 w;
        w.x = *(uint32_t*)&lo;
        w.y = *(uint32_t*)&hi;
        *(uint2*)(&g_pair[(size_t)gm * 128 + 64 + (cq >> 1)]) = w;
        *(uint2*)(&Asm[row][cq >> 1]) = w;
    }

    // ---- Prologue: ALL 16 B stages (both W1 halves), half2 kpairs -------------
    {
        const int b_kp = tid >> 5;           // 0..7
        const int b_nq = (tid & 31) * 4;     // 0..124
#pragma unroll
        for (int t = 0; t < 16; t++) {
            const float* Bs = W1 + (size_t)(t >> 3) * (DIM * DIM)
                                 + (size_t)((t & 7) * 16) * DIM;
            float4 vb0 = *(const float4*)(Bs + (size_t)(2 * b_kp) * DIM + b_nq);
            float4 vb1 = *(const float4*)(Bs + (size_t)(2 * b_kp + 1) * DIM + b_nq);
            __half2 h0 = __floats2half2_rn(vb0.x, vb1.x);
            __half2 h1 = __floats2half2_rn(vb0.y, vb1.y);
            __half2 h2 = __floats2half2_rn(vb0.z, vb1.z);
            __half2 h3 = __floats2half2_rn(vb0.w, vb1.w);
            uint4 tt;
            tt.x = *(uint32_t*)&h0;
            tt.y = *(uint32_t*)&h1;
            tt.z = *(uint32_t*)&h2;
            tt.w = *(uint32_t*)&h3;
            *(uint4*)(&Bsm[t][b_kp][b_nq]) = tt;
        }
    }
    __syncthreads();   // the ONLY barrier

    float acc[4][4][4];
#pragma unroll
    for (int tm = 0; tm < 4; tm++)
#pragma unroll
        for (int tn = 0; tn < 4; tn++)
#pragma unroll
            for (int q = 0; q < 4; q++) acc[tm][tn][q] = 0.f;

    // Epilogues (acc in registers; no smem deps).
    auto epilogue = [&](int half) {
#pragma unroll
        for (int tm = 0; tm < 4; tm++) {
            const int gmA = m0 + warpm + tm * 16 + r;
            const int gmB = gmA + 8;
#pragma unroll
            for (int tn = 0; tn < 4; tn++) {
                const int nc = warpn + tn * 8 + 2 * c;
                if (half == 0) {
                    const float bx = sb1[nc], by = sb1[nc + 1];
                    if (gmA < N_NODES) {
                        float2 v = make_float2(acc[tm][tn][0] + bx, acc[tm][tn][1] + by);
                        *(float2*)(g_X1 + (size_t)gmA * DIM + nc) = v;
                    }
                    if (gmB < N_NODES) {
                        float2 v = make_float2(acc[tm][tn][2] + bx, acc[tm][tn][3] + by);
                        *(float2*)(g_X1 + (size_t)gmB * DIM + nc) = v;
                    }
                } else {
                    if (gmA < N_NODES) {
                        __nv_bfloat162 h = __floats2bfloat162_rn(acc[tm][tn][0], acc[tm][tn][1]);
                        g_pair[(size_t)gmA * 128 + (nc >> 1)] = *(uint32_t*)&h;
                    }
                    if (gmB < N_NODES) {
                        __nv_bfloat162 h = __floats2bfloat162_rn(acc[tm][tn][2], acc[tm][tn][3]);
                        g_pair[(size_t)gmB * 128 + (nc >> 1)] = *(uint32_t*)&h;
                    }
                }
            }
        }
    };

    // ---- Barrier-free mainloop: 16 chunks x 16 mma -----------------------------
#pragma unroll 2
    for (int t = 0; t < 16; t++) {
        const int kpb = (t & 7) * 8;            // kpair base within Asm row

        uint32_t af[4][4];
#pragma unroll
        for (int tm = 0; tm < 4; tm++) {
            const int mr = warpm + tm * 16;
            af[tm][0] = Asm[mr + r    ][kpb + c];
            af[tm][1] = Asm[mr + r + 8][kpb + c];
            af[tm][2] = Asm[mr + r    ][kpb + c + 4];
            af[tm][3] = Asm[mr + r + 8][kpb + c + 4];
        }
        uint32_t bf[4][2];
#pragma unroll
        for (int tn = 0; tn < 4; tn++) {
            const int nc = warpn + tn * 8;
            bf[tn][0] = Bsm[t][c    ][nc + r];
            bf[tn][1] = Bsm[t][c + 4][nc + r];
        }
#pragma unroll
        for (int tm = 0; tm < 4; tm++)
#pragma unroll
            for (int tn = 0; tn < 4; tn++)
                mma_f16(acc[tm][tn], af[tm], bf[tn]);

        if (t == 7) {
            epilogue(0);                        // overlaps half-1 K-sweep
#pragma unroll
            for (int tm = 0; tm < 4; tm++)
#pragma unroll
                for (int tn = 0; tn < 4; tn++)
#pragma unroll
                    for (int q = 0; q < 4; q++) acc[tm][tn][q] = 0.f;
        }
    }
    epilogue(1);
}

// ---------------------------------------------------------------------------
// Kernel 2: HALF-WARP per node, two-phase softmax, register-lean (unchanged
// from the measured 82.4 us config).
// ---------------------------------------------------------------------------
__global__ __launch_bounds__(128) void attend_kernel(const int* __restrict__ nbr,
                                                     const float* __restrict__ W2,
                                                     float* __restrict__ out) {
    __shared__ float s_w2[DIM];
    const int tid = threadIdx.x;
    s_w2[tid] = W2[tid] * 1.4426950408889634f;   // fold log2e: exp(s) = exp2(s')
    __syncthreads();

    const int n = blockIdx.x * 8 + (tid >> 4);   // node per half-warp (exact: 100000/8)
    const int sl = tid & 15;                     // sub-lane: dims sl*8..sl*8+7
    const u64 pol = make_evict_last_policy();

    const float4 x1a = __ldcs((const float4*)(g_X1 + (size_t)n * DIM + sl * 8));
    const float4 x1b = __ldcs((const float4*)(g_X1 + (size_t)n * DIM + sl * 8 + 4));
    const float4 w2a = *(const float4*)(s_w2 + sl * 8);
    const float4 w2b = *(const float4*)(s_w2 + sl * 8 + 4);

    const uint32_t sl4 = (uint32_t)sl << 2;

    // Phase A: scores (exp2-domain, unnormalized; shift-invariance => no max
    // subtraction needed at this score scale).
    float sc[KNB];
    float rz = 0.f;
#pragma unroll
    for (int g = 0; g < 4; g++) {
        const int4 jv = __ldg((const int4*)(nbr + (size_t)n * KNB + g * 4));
        uint4 xq[4];
        xq[0] = ldg_keep4u(g_pair + (((uint32_t)jv.x << 7) + sl4), pol);
        xq[1] = ldg_keep4u(g_pair + (((uint32_t)jv.y << 7) + sl4), pol);
        xq[2] = ldg_keep4u(g_pair + (((uint32_t)jv.z << 7) + sl4), pol);
        xq[3] = ldg_keep4u(g_pair + (((uint32_t)jv.w << 7) + sl4), pol);

        float p[4];
#pragma unroll
        for (int t = 0; t < 4; t++) {
            const float2 a0 = __bfloat1622float2(*(const __nv_bfloat162*)&xq[t].x);
            const float2 a1 = __bfloat1622float2(*(const __nv_bfloat162*)&xq[t].y);
            const float2 a2 = __bfloat1622float2(*(const __nv_bfloat162*)&xq[t].z);
            const float2 a3 = __bfloat1622float2(*(const __nv_bfloat162*)&xq[t].w);
            float s = fmaxf(x1a.x + a0.x, 0.f) * w2a.x;
            s = fmaf(fmaxf(x1a.y + a0.y, 0.f), w2a.y, s);
            s = fmaf(fmaxf(x1a.z + a1.x, 0.f), w2a.z, s);
            s = fmaf(fmaxf(x1a.w + a1.y, 0.f), w2a.w, s);
            s = fmaf(fmaxf(x1b.x + a2.x, 0.f), w2b.x, s);
            s = fmaf(fmaxf(x1b.y + a2.y, 0.f), w2b.y, s);
            s = fmaf(fmaxf(x1b.z + a3.x, 0.f), w2b.z, s);
            s = fmaf(fmaxf(x1b.w + a3.y, 0.f), w2b.w, s);
            p[t] = s;
        }
#pragma unroll
        for (int d = 8; d > 0; d >>= 1) {
            p[0] += __shfl_xor_sync(0xffffffffu, p[0], d);
            p[1] += __shfl_xor_sync(0xffffffffu, p[1], d);
            p[2] += __shfl_xor_sync(0xffffffffu, p[2], d);
            p[3] += __shfl_xor_sync(0xffffffffu, p[3], d);
        }
#pragma unroll
        for (int t = 0; t < 4; t++) {
            const float e = exp2f(p[t]);
            sc[g * 4 + t] = e;
            rz += e;
        }
    }

    const float inv = 1.f / rz;
#pragma unroll
    for (int k = 0; k < KNB; k++) sc[k] *= inv;

    // Phase B: weighted accumulate over fp16 lat halves (nbr rows L1-hot).
    float acc[8];
#pragma unroll
    for (int i = 0; i < 8; i++) acc[i] = 0.f;

#pragma unroll
    for (int g = 0; g < 4; g++) {
        const int4 jv = __ldg((const int4*)(nbr + (size_t)n * KNB + g * 4));
        uint4 lq[4];
        lq[0] = ldg_keep4u(g_pair + (((uint32_t)jv.x << 7) + sl4) + 64, pol);
        lq[1] = ldg_keep4u(g_pair + (((uint32_t)jv.y << 7) + sl4) + 64, pol);
        lq[2] = ldg_keep4u(g_pair + (((uint32_t)jv.z << 7) + sl4) + 64, pol);
        lq[3] = ldg_keep4u(g_pair + (((uint32_t)jv.w << 7) + sl4) + 64, pol);
#pragma unroll
        for (int t = 0; t < 4; t++) {
            const float2 l0 = __half22float2(*(const __half2*)&lq[t].x);
            const float2 l1 = __half22float2(*(const __half2*)&lq[t].y);
            const float2 l2 = __half22float2(*(const __half2*)&lq[t].z);
            const float2 l3 = __half22float2(*(const __half2*)&lq[t].w);
            const float w = sc[g * 4 + t];
            acc[0] = fmaf(w, l0.x, acc[0]);
            acc[1] = fmaf(w, l0.y, acc[1]);
            acc[2] = fmaf(w, l1.x, acc[2]);
            acc[3] = fmaf(w, l1.y, acc[3]);
            acc[4] = fmaf(w, l2.x, acc[4]);
            acc[5] = fmaf(w, l2.y, acc[5]);
            acc[6] = fmaf(w, l3.x, acc[6]);
            acc[7] = fmaf(w, l3.y, acc[7]);
        }
    }

    float4 o0, o1;
    o0.x = acc[0]; o0.y = acc[1]; o0.z = acc[2]; o0.w = acc[3];
    o1.x = acc[4]; o1.y = acc[5]; o1.z = acc[6]; o1.w = acc[7];
    __stcs((float4*)(out + (size_t)n * DIM + sl * 8), o0);
    __stcs((float4*)(out + (size_t)n * DIM + sl * 8 + 4), o1);
}

// ---------------------------------------------------------------------------
// Launch
// ---------------------------------------------------------------------------
extern "C" void kernel_launch(void* const* d_in, const int* in_sizes, int n_in,
                              void* d_out, int out_size) {
    const float* latents   = (const float*)d_in[0];
    const int*   neighbors = (const int*)d_in[1];   // int32 (JAX x64-disabled)
    const float* W1        = (const float*)d_in[2];
    const float* b1        = (const float*)d_in[3];
    const float* W2        = (const float*)d_in[4];
    // d_in[5] = b2: cancels in softmax.
    float* out = (float*)d_out;

    (void)in_sizes; (void)n_in; (void)out_size;

    static bool attr_done = false;
    if (!attr_done) {
        cudaFuncSetAttribute(mlp1_gemm_mma,
                             cudaFuncAttributeMaxDynamicSharedMemorySize, SM_TOTAL);
        attr_done = true;
    }

    const int gemm_blocks = (N_NODES + 127) / 128;   // 782
    mlp1_gemm_mma<<<gemm_blocks, 256, SM_TOTAL>>>(latents, W1, b1);

    const int blocks = N_NODES / 8;   // 12500, exact: 8 nodes (half-warps) per block
    attend_kernel<<<blocks, 128>>>(neighbors, W2, out);
}